// round 1
// baseline (speedup 1.0000x reference)
#include <cuda_runtime.h>
#include <cuda_bf16.h>
#include <math.h>

// Problem constants (fixed shapes from reference)
#define BATCH   2
#define N_SEQ   2048
#define EMB     512
#define NHEAD   8
#define HD      64
#define M_ROWS  (BATCH * N_SEQ)   // 4096

// ---------------- scratch (__device__ globals; no allocation allowed) -------
__device__ float g_Q[M_ROWS * EMB];
__device__ float g_K[M_ROWS * EMB];
__device__ float g_V[M_ROWS * EMB];
__device__ float g_A[M_ROWS * EMB];        // attention output, [B,N,H*Dv]
__device__ float g_Vsum[BATCH * NHEAD * HD];

// ---------------- SGEMM: C[m,n] = sum_k X[m,k]*W[n,k] + bias[n] -------------
// X: [M,K] row-major, W: [N,K] row-major (torch Linear weight), both K-contig.
#define BM 128
#define BN 128
#define BK 8
#define TM 8
#define TN 8

__global__ __launch_bounds__(256, 2)
void sgemm_bias_kernel(const float* __restrict__ X, const float* __restrict__ W,
                       const float* __restrict__ bias, float* __restrict__ C,
                       int M, int N, int K) {
    __shared__ float As[BK][BM];
    __shared__ float Bs[BK][BN];

    const int bx = blockIdx.x;          // N tile
    const int by = blockIdx.y;          // M tile
    const int tid = threadIdx.x;
    const int tx = tid % 16;            // 0..15 (n)
    const int ty = tid / 16;            // 0..15 (m)

    const float* Xb = X + (size_t)by * BM * K;
    const float* Wb = W + (size_t)bx * BN * K;

    const int lrow = tid >> 1;          // 0..127
    const int lk4  = (tid & 1) * 4;     // 0 or 4

    float acc[TM][TN];
    #pragma unroll
    for (int i = 0; i < TM; i++)
        #pragma unroll
        for (int j = 0; j < TN; j++) acc[i][j] = 0.f;

    for (int k0 = 0; k0 < K; k0 += BK) {
        float4 av = *(const float4*)(Xb + (size_t)lrow * K + k0 + lk4);
        float4 bv = *(const float4*)(Wb + (size_t)lrow * K + k0 + lk4);
        As[lk4 + 0][lrow] = av.x; As[lk4 + 1][lrow] = av.y;
        As[lk4 + 2][lrow] = av.z; As[lk4 + 3][lrow] = av.w;
        Bs[lk4 + 0][lrow] = bv.x; Bs[lk4 + 1][lrow] = bv.y;
        Bs[lk4 + 2][lrow] = bv.z; Bs[lk4 + 3][lrow] = bv.w;
        __syncthreads();

        #pragma unroll
        for (int k = 0; k < BK; k++) {
            float a[TM], b[TN];
            float4 a0 = *(const float4*)&As[k][ty * TM];
            float4 a1 = *(const float4*)&As[k][ty * TM + 4];
            float4 b0 = *(const float4*)&Bs[k][tx * TN];
            float4 b1 = *(const float4*)&Bs[k][tx * TN + 4];
            a[0]=a0.x; a[1]=a0.y; a[2]=a0.z; a[3]=a0.w;
            a[4]=a1.x; a[5]=a1.y; a[6]=a1.z; a[7]=a1.w;
            b[0]=b0.x; b[1]=b0.y; b[2]=b0.z; b[3]=b0.w;
            b[4]=b1.x; b[5]=b1.y; b[6]=b1.z; b[7]=b1.w;
            #pragma unroll
            for (int i = 0; i < TM; i++)
                #pragma unroll
                for (int j = 0; j < TN; j++)
                    acc[i][j] = fmaf(a[i], b[j], acc[i][j]);
        }
        __syncthreads();
    }

    // epilogue: add bias, float4 stores
    const int nbase = bx * BN + tx * TN;
    float4 bb0 = *(const float4*)(bias + nbase);
    float4 bb1 = *(const float4*)(bias + nbase + 4);
    #pragma unroll
    for (int i = 0; i < TM; i++) {
        int m = by * BM + ty * TM + i;
        float4 o0, o1;
        o0.x = acc[i][0] + bb0.x; o0.y = acc[i][1] + bb0.y;
        o0.z = acc[i][2] + bb0.z; o0.w = acc[i][3] + bb0.w;
        o1.x = acc[i][4] + bb1.x; o1.y = acc[i][5] + bb1.y;
        o1.z = acc[i][6] + bb1.z; o1.w = acc[i][7] + bb1.w;
        *(float4*)(C + (size_t)m * N + nbase)     = o0;
        *(float4*)(C + (size_t)m * N + nbase + 4) = o1;
    }
}

// ---------------- Vsum over sequence per (b,h) -------------------------------
__global__ void vsum_kernel(const float* __restrict__ V, float* __restrict__ Vsum) {
    const int bh = blockIdx.x;          // 0..15
    const int b = bh / NHEAD, h = bh % NHEAD;
    const int d = threadIdx.x % HD;     // 0..63
    const int g = threadIdx.x / HD;     // 0..3
    __shared__ float red[4][HD];

    float s = 0.f;
    const size_t base = (size_t)b * N_SEQ * EMB + h * HD + d;
    for (int i = g; i < N_SEQ; i += 4)
        s += V[base + (size_t)i * EMB];
    red[g][d] = s;
    __syncthreads();
    if (g == 0)
        Vsum[bh * HD + d] = red[0][d] + red[1][d] + red[2][d] + red[3][d];
}

// ---------------- fused "softmax" + value combine ----------------------------
// out_r = (Vsum + sum_c (exp(s_c)-1) * V_c) / (N + sum_c (exp(s_c)-1))
// where s_c = q_r . k_{r+c-1} (c=0,1,2), V_c = V row at position c (column idx!)
__global__ void attn_kernel(const float* __restrict__ Q, const float* __restrict__ K,
                            const float* __restrict__ V, const float* __restrict__ Vsum,
                            float* __restrict__ out) {
    const int bh = blockIdx.x;                  // 0..15
    const int b = bh / NHEAD, h = bh % NHEAD;
    const int chunk = blockIdx.y;               // 0..15
    const int warp = threadIdx.x >> 5;
    const int lane = threadIdx.x & 31;

    __shared__ float sV[3][HD];
    __shared__ float sVs[HD];

    const size_t base = (size_t)b * N_SEQ * EMB + h * HD;
    if (threadIdx.x < HD) {
        sVs[threadIdx.x] = Vsum[bh * HD + threadIdx.x];
    } else if (threadIdx.x < HD + 3 * HD) {
        int t = threadIdx.x - HD;
        sV[t / HD][t % HD] = V[base + (size_t)(t / HD) * EMB + (t % HD)];
    }
    __syncthreads();

    const int rows_per_block = N_SEQ / 16;      // 128
    const int r0 = chunk * rows_per_block;

    for (int r = r0 + warp; r < r0 + rows_per_block; r += 8) {
        const float* qp = Q + base + (size_t)r * EMB;
        const float q0 = qp[lane];
        const float q1 = qp[lane + 32];

        float e[3];
        #pragma unroll
        for (int c = 0; c < 3; c++) {
            const int kr = r + c - 1;
            float v = 0.f;
            if (kr >= 0 && kr < N_SEQ) {
                const float* kp = K + base + (size_t)kr * EMB;
                v = q0 * kp[lane] + q1 * kp[lane + 32];
            }
            #pragma unroll
            for (int off = 16; off; off >>= 1)
                v += __shfl_xor_sync(0xffffffff, v, off);
            e[c] = (kr >= 0 && kr < N_SEQ) ? (expf(v) - 1.f) : 0.f;
        }

        const float inv = 1.f / ((float)N_SEQ + e[0] + e[1] + e[2]);
        float* op = out + base + (size_t)r * EMB;
        #pragma unroll
        for (int dd = 0; dd < 2; dd++) {
            const int d = lane + dd * 32;
            float o = sVs[d] + e[0] * sV[0][d] + e[1] * sV[1][d] + e[2] * sV[2][d];
            op[d] = o * inv;
        }
    }
}

// ---------------- launch ------------------------------------------------------
extern "C" void kernel_launch(void* const* d_in, const int* in_sizes, int n_in,
                              void* d_out, int out_size) {
    const float* x  = (const float*)d_in[0];
    const float* Wq = (const float*)d_in[1];
    const float* bq = (const float*)d_in[2];
    const float* Wk = (const float*)d_in[3];
    const float* bk = (const float*)d_in[4];
    const float* Wv = (const float*)d_in[5];
    const float* bv = (const float*)d_in[6];
    const float* Wo = (const float*)d_in[7];
    const float* bo = (const float*)d_in[8];
    float* outp = (float*)d_out;

    float *Qp, *Kp, *Vp, *Ap, *Vsp;
    cudaGetSymbolAddress((void**)&Qp,  g_Q);
    cudaGetSymbolAddress((void**)&Kp,  g_K);
    cudaGetSymbolAddress((void**)&Vp,  g_V);
    cudaGetSymbolAddress((void**)&Ap,  g_A);
    cudaGetSymbolAddress((void**)&Vsp, g_Vsum);

    dim3 ggrid(EMB / BN, M_ROWS / BM);   // (4, 32)

    sgemm_bias_kernel<<<ggrid, 256>>>(x, Wq, bq, Qp, M_ROWS, EMB, EMB);
    sgemm_bias_kernel<<<ggrid, 256>>>(x, Wk, bk, Kp, M_ROWS, EMB, EMB);
    sgemm_bias_kernel<<<ggrid, 256>>>(x, Wv, bv, Vp, M_ROWS, EMB, EMB);

    vsum_kernel<<<BATCH * NHEAD, 256>>>(Vp, Vsp);
    attn_kernel<<<dim3(BATCH * NHEAD, 16), 256>>>(Qp, Kp, Vp, Vsp, Ap);

    sgemm_bias_kernel<<<ggrid, 256>>>(Ap, Wo, bo, outp, M_ROWS, EMB, EMB);
}

// round 2
// speedup vs baseline: 1.8732x; 1.8732x over previous
#include <cuda_runtime.h>
#include <cuda_bf16.h>
#include <math.h>

// Problem constants (fixed shapes from reference)
#define BATCH   2
#define N_SEQ   2048
#define EMB     512
#define NHEAD   8
#define HD      64
#define M_ROWS  (BATCH * N_SEQ)   // 4096

// ---------------- scratch (__device__ globals; no allocation allowed) -------
__device__ float g_Q[M_ROWS * EMB];
__device__ float g_K[M_ROWS * EMB];
__device__ float g_xpart[BATCH * 32 * EMB];          // partial x sums
__device__ float g_basis[BATCH * 4 * EMB];           // [b][j][512]: Vsum, V0, V1, V2
__device__ float g_U[BATCH * NHEAD * 4 * EMB];       // [b][h][j][512]
__device__ float g_coef[M_ROWS * NHEAD * 4];         // [b*N+r][h*4+j]

// ---------------- SGEMM: Q,K = x@W.T + b in one launch (z selects) ----------
#define BM 128
#define BN 128
#define BK 8
#define TM 8
#define TN 8

__global__ __launch_bounds__(256, 2)
void sgemm_qk_kernel(const float* __restrict__ X,
                     const float* __restrict__ Wq, const float* __restrict__ bq,
                     const float* __restrict__ Wk, const float* __restrict__ bk,
                     float* __restrict__ Qout, float* __restrict__ Kout) {
    __shared__ float As[BK][BM];
    __shared__ float Bs[BK][BN];

    const float* W    = blockIdx.z ? Wk   : Wq;
    const float* bias = blockIdx.z ? bk   : bq;
    float*       C    = blockIdx.z ? Kout : Qout;

    const int K = EMB, N = EMB;
    const int bx = blockIdx.x;          // N tile
    const int by = blockIdx.y;          // M tile
    const int tid = threadIdx.x;
    const int tx = tid % 16;            // 0..15 (n)
    const int ty = tid / 16;            // 0..15 (m)

    const float* Xb = X + (size_t)by * BM * K;
    const float* Wb = W + (size_t)bx * BN * K;

    const int lrow = tid >> 1;          // 0..127
    const int lk4  = (tid & 1) * 4;     // 0 or 4

    float acc[TM][TN];
    #pragma unroll
    for (int i = 0; i < TM; i++)
        #pragma unroll
        for (int j = 0; j < TN; j++) acc[i][j] = 0.f;

    for (int k0 = 0; k0 < K; k0 += BK) {
        float4 av = *(const float4*)(Xb + (size_t)lrow * K + k0 + lk4);
        float4 bv = *(const float4*)(Wb + (size_t)lrow * K + k0 + lk4);
        As[lk4 + 0][lrow] = av.x; As[lk4 + 1][lrow] = av.y;
        As[lk4 + 2][lrow] = av.z; As[lk4 + 3][lrow] = av.w;
        Bs[lk4 + 0][lrow] = bv.x; Bs[lk4 + 1][lrow] = bv.y;
        Bs[lk4 + 2][lrow] = bv.z; Bs[lk4 + 3][lrow] = bv.w;
        __syncthreads();

        #pragma unroll
        for (int k = 0; k < BK; k++) {
            float a[TM], b[TN];
            float4 a0 = *(const float4*)&As[k][ty * TM];
            float4 a1 = *(const float4*)&As[k][ty * TM + 4];
            float4 b0 = *(const float4*)&Bs[k][tx * TN];
            float4 b1 = *(const float4*)&Bs[k][tx * TN + 4];
            a[0]=a0.x; a[1]=a0.y; a[2]=a0.z; a[3]=a0.w;
            a[4]=a1.x; a[5]=a1.y; a[6]=a1.z; a[7]=a1.w;
            b[0]=b0.x; b[1]=b0.y; b[2]=b0.z; b[3]=b0.w;
            b[4]=b1.x; b[5]=b1.y; b[6]=b1.z; b[7]=b1.w;
            #pragma unroll
            for (int i = 0; i < TM; i++)
                #pragma unroll
                for (int j = 0; j < TN; j++)
                    acc[i][j] = fmaf(a[i], b[j], acc[i][j]);
        }
        __syncthreads();
    }

    const int nbase = bx * BN + tx * TN;
    float4 bb0 = *(const float4*)(bias + nbase);
    float4 bb1 = *(const float4*)(bias + nbase + 4);
    #pragma unroll
    for (int i = 0; i < TM; i++) {
        int m = by * BM + ty * TM + i;
        float4 o0, o1;
        o0.x = acc[i][0] + bb0.x; o0.y = acc[i][1] + bb0.y;
        o0.z = acc[i][2] + bb0.z; o0.w = acc[i][3] + bb0.w;
        o1.x = acc[i][4] + bb1.x; o1.y = acc[i][5] + bb1.y;
        o1.z = acc[i][6] + bb1.z; o1.w = acc[i][7] + bb1.w;
        *(float4*)(C + (size_t)m * N + nbase)     = o0;
        *(float4*)(C + (size_t)m * N + nbase + 4) = o1;
    }
}

// ---------------- partial sums of x over n ------------------------------------
__global__ __launch_bounds__(256)
void xpart_kernel(const float* __restrict__ x, float* __restrict__ xpart) {
    const int b = blockIdx.x;                 // 0..1
    const int c = blockIdx.y;                 // 0..31 (64-row chunk)
    const int t = threadIdx.x;                // 0..255
    const size_t base = (size_t)b * N_SEQ * EMB + (size_t)c * 64 * EMB;
    float s0 = 0.f, s1 = 0.f;
    for (int n = 0; n < 64; n++) {
        s0 += x[base + (size_t)n * EMB + t];
        s1 += x[base + (size_t)n * EMB + t + 256];
    }
    xpart[(size_t)(b * 32 + c) * EMB + t]       = s0;
    xpart[(size_t)(b * 32 + c) * EMB + t + 256] = s1;
}

// ---------------- basis vectors: Vsum (j=0) and V rows 0..2 (j=1..3) ---------
__global__ __launch_bounds__(256)
void basis_kernel(const float* __restrict__ x, const float* __restrict__ xpart,
                  const float* __restrict__ Wv, const float* __restrict__ bv,
                  float* __restrict__ basis) {
    const int b = blockIdx.x;   // 0..1
    const int j = blockIdx.y;   // 0..3
    const int t = threadIdx.x;  // 0..255
    __shared__ float vec[EMB];

    if (j == 0) {
        float s0 = 0.f, s1 = 0.f;
        for (int c = 0; c < 32; c++) {
            s0 += xpart[(size_t)(b * 32 + c) * EMB + t];
            s1 += xpart[(size_t)(b * 32 + c) * EMB + t + 256];
        }
        vec[t] = s0; vec[t + 256] = s1;
    } else {
        const size_t rb = ((size_t)b * N_SEQ + (j - 1)) * EMB;
        vec[t]       = x[rb + t];
        vec[t + 256] = x[rb + t + 256];
    }
    __syncthreads();

    const float bscale = (j == 0) ? (float)N_SEQ : 1.f;
    #pragma unroll
    for (int rep = 0; rep < 2; rep++) {
        const int eo = t + rep * 256;
        float acc = bv[eo] * bscale;
        const float4* wr = (const float4*)(Wv + (size_t)eo * EMB);
        #pragma unroll 4
        for (int e4 = 0; e4 < EMB / 4; e4++) {
            float4 w = wr[e4];
            const float* v = &vec[e4 * 4];
            acc += w.x * v[0] + w.y * v[1] + w.z * v[2] + w.w * v[3];
        }
        basis[(size_t)(b * 4 + j) * EMB + eo] = acc;
    }
}

// ---------------- U[b][h][j][e] = sum_d basis[b][j][h*64+d] * Wo[e][h*64+d] --
__global__ __launch_bounds__(256)
void u_kernel(const float* __restrict__ basis, const float* __restrict__ Wo,
              float* __restrict__ U) {
    const int bh = blockIdx.x;          // 0..15
    const int b = bh >> 3, h = bh & 7;
    const int t = threadIdx.x;          // 0..255
    __shared__ float bs[4][HD];
    {
        // 256 threads load exactly 4*64 = 256 elements
        const int j = t / HD, d = t % HD;
        bs[j][d] = basis[(size_t)(b * 4 + j) * EMB + h * HD + d];
    }
    __syncthreads();

    #pragma unroll
    for (int j = 0; j < 4; j++) {
        #pragma unroll
        for (int rep = 0; rep < 2; rep++) {
            const int eo = t + rep * 256;
            const float4* wr = (const float4*)(Wo + (size_t)eo * EMB + h * HD);
            float acc = 0.f;
            #pragma unroll
            for (int d4 = 0; d4 < HD / 4; d4++) {
                float4 w = wr[d4];
                acc += w.x * bs[j][d4 * 4 + 0] + w.y * bs[j][d4 * 4 + 1]
                     + w.z * bs[j][d4 * 4 + 2] + w.w * bs[j][d4 * 4 + 3];
            }
            U[((size_t)(b * NHEAD + h) * 4 + j) * EMB + eo] = acc;
        }
    }
}

// ---------------- coefficients: per (b,h,r) the 4 combine weights ------------
__global__ __launch_bounds__(256)
void coef_kernel(const float* __restrict__ Q, const float* __restrict__ K,
                 float* __restrict__ coef) {
    const int bh = blockIdx.x;                  // 0..15
    const int b = bh >> 3, h = bh & 7;
    const int r0 = blockIdx.y * 64;             // 32 chunks of 64 rows
    const int warp = threadIdx.x >> 5;
    const int lane = threadIdx.x & 31;
    const size_t base = (size_t)b * N_SEQ * EMB + h * HD;

    for (int rr = warp; rr < 64; rr += 8) {
        const int r = r0 + rr;
        const float* qp = Q + base + (size_t)r * EMB;
        const float q0 = qp[lane];
        const float q1 = qp[lane + 32];

        float e[3];
        #pragma unroll
        for (int c = 0; c < 3; c++) {
            const int kr = r + c - 1;
            const bool valid = (kr >= 0 && kr < N_SEQ);
            float v = 0.f;
            if (valid) {
                const float* kp = K + base + (size_t)kr * EMB;
                v = q0 * kp[lane] + q1 * kp[lane + 32];
            }
            #pragma unroll
            for (int off = 16; off; off >>= 1)
                v += __shfl_xor_sync(0xffffffff, v, off);
            e[c] = valid ? (expf(v) - 1.f) : 0.f;
        }

        const float inv = 1.f / ((float)N_SEQ + e[0] + e[1] + e[2]);
        if (lane < 4) {
            const float val = (lane == 0) ? inv : inv * e[lane - 1];
            coef[((size_t)(b * N_SEQ + r) * NHEAD + h) * 4 + lane] = val;
        }
    }
}

// ---------------- out[b,r,:] = bo + sum_{h,j} coef * U -----------------------
__global__ __launch_bounds__(256)
void out_kernel(const float* __restrict__ U, const float* __restrict__ coef,
                const float* __restrict__ bo, float* __restrict__ out) {
    const int blk = blockIdx.x;                 // 0..255
    const int b = blk >> 7;                     // 0..1
    const int r0 = (blk & 127) * 16;            // 16 rows per block
    const int t = threadIdx.x;                  // 0..255

    // keep the 32 U values for columns t and t+256 in registers
    float u0[32], u1[32];
    #pragma unroll
    for (int hj = 0; hj < 32; hj++) {
        u0[hj] = U[((size_t)b * 32 + hj) * EMB + t];
        u1[hj] = U[((size_t)b * 32 + hj) * EMB + t + 256];
    }
    const float bo0 = bo[t], bo1 = bo[t + 256];

    __shared__ float sc[16][32];
    {
        const size_t cb = (size_t)(b * N_SEQ + r0) * 32;
        int i0 = t;        sc[i0 / 32][i0 % 32] = coef[cb + i0];
        int i1 = t + 256;  sc[i1 / 32][i1 % 32] = coef[cb + i1];
    }
    __syncthreads();

    for (int rr = 0; rr < 16; rr++) {
        float a0 = bo0, a1 = bo1;
        #pragma unroll
        for (int hj = 0; hj < 32; hj++) {
            const float c = sc[rr][hj];
            a0 = fmaf(c, u0[hj], a0);
            a1 = fmaf(c, u1[hj], a1);
        }
        const size_t ob = (size_t)(b * N_SEQ + r0 + rr) * EMB;
        out[ob + t]       = a0;
        out[ob + t + 256] = a1;
    }
}

// ---------------- launch ------------------------------------------------------
extern "C" void kernel_launch(void* const* d_in, const int* in_sizes, int n_in,
                              void* d_out, int out_size) {
    const float* x  = (const float*)d_in[0];
    const float* Wq = (const float*)d_in[1];
    const float* bq = (const float*)d_in[2];
    const float* Wk = (const float*)d_in[3];
    const float* bk = (const float*)d_in[4];
    const float* Wv = (const float*)d_in[5];
    const float* bv = (const float*)d_in[6];
    const float* Wo = (const float*)d_in[7];
    const float* bo = (const float*)d_in[8];
    float* outp = (float*)d_out;

    float *Qp, *Kp, *xpp, *bsp, *Up, *cfp;
    cudaGetSymbolAddress((void**)&Qp,  g_Q);
    cudaGetSymbolAddress((void**)&Kp,  g_K);
    cudaGetSymbolAddress((void**)&xpp, g_xpart);
    cudaGetSymbolAddress((void**)&bsp, g_basis);
    cudaGetSymbolAddress((void**)&Up,  g_U);
    cudaGetSymbolAddress((void**)&cfp, g_coef);

    // small prep chain (independent of Q/K GEMM)
    xpart_kernel<<<dim3(BATCH, 32), 256>>>(x, xpp);
    basis_kernel<<<dim3(BATCH, 4), 256>>>(x, xpp, Wv, bv, bsp);
    u_kernel<<<BATCH * NHEAD, 256>>>(bsp, Wo, Up);

    // the only remaining heavy work: Q and K projections (one fused launch)
    sgemm_qk_kernel<<<dim3(EMB / BN, M_ROWS / BM, 2), 256>>>(x, Wq, bq, Wk, bk, Qp, Kp);

    coef_kernel<<<dim3(BATCH * NHEAD, 32), 256>>>(Qp, Kp, cfp);
    out_kernel<<<256, 256>>>(Up, cfp, bo, outp);
}

// round 5
// speedup vs baseline: 5.1332x; 2.7403x over previous
#include <cuda_runtime.h>
#include <cuda_bf16.h>
#include <math.h>
#include <stdint.h>

// Problem constants
#define BATCH   2
#define N_SEQ   2048
#define EMB     512
#define NHEAD   8
#define HD      64
#define M_ROWS  (BATCH * N_SEQ)   // 4096

// ---------------- scratch ----------------------------------------------------
__device__ float g_Q[M_ROWS * EMB];
__device__ float g_K[M_ROWS * EMB];
__device__ float g_xpart[BATCH * 64 * EMB];
__device__ float g_basis[BATCH * 4 * EMB];
__device__ float g_U[BATCH * NHEAD * 4 * EMB];
__device__ float g_coef[M_ROWS * NHEAD * 4];

// ---------------- helpers ------------------------------------------------------
__device__ __forceinline__ uint32_t smem_u32(const void* p) {
    uint32_t a;
    asm("{ .reg .u64 t; cvta.to.shared.u64 t, %1; cvt.u32.u64 %0, t; }"
        : "=r"(a) : "l"(p));
    return a;
}

__device__ __forceinline__ void cp16(uint32_t dst, const void* src) {
    asm volatile("cp.async.cg.shared.global [%0], [%1], 16;"
                 :: "r"(dst), "l"(src) : "memory");
}
__device__ __forceinline__ void cp_commit() {
    asm volatile("cp.async.commit_group;" ::: "memory");
}
template <int N> __device__ __forceinline__ void cp_wait() {
    asm volatile("cp.async.wait_group %0;" :: "n"(N) : "memory");
}

__device__ __forceinline__ uint32_t f2tf32(float f) {
    uint32_t u;
    asm("cvt.rna.tf32.f32 %0, %1;" : "=r"(u) : "f"(f));
    return u;
}

__device__ __forceinline__ void mma_tf32(float d[4], const uint32_t a[4],
                                         const uint32_t b[2]) {
    asm volatile(
        "mma.sync.aligned.m16n8k8.row.col.f32.tf32.tf32.f32 "
        "{%0,%1,%2,%3}, {%4,%5,%6,%7}, {%8,%9}, {%0,%1,%2,%3};"
        : "+f"(d[0]), "+f"(d[1]), "+f"(d[2]), "+f"(d[3])
        : "r"(a[0]), "r"(a[1]), "r"(a[2]), "r"(a[3]), "r"(b[0]), "r"(b[1]));
}

// ---------------- tf32 mma.sync GEMM: Q,K = X @ W.T + b -----------------------
// CTA tile 128x128, BK=32, 8 warps (2x4), warp tile 64x32, double-buffered.
#define BM 128
#define BN 128
#define BK 32
#define SA 36                      // padded row stride (floats): conflict-free frags
#define NKITER (EMB / BK)          // 16
#define TILE_FLOATS (128 * SA)     // per tile per stage
#define GEMM_SMEM (4 * TILE_FLOATS * 4)   // A/B x 2 stages = 73728 B

__global__ __launch_bounds__(256, 2)
void qk_gemm_tf32mma(const float* __restrict__ x,
                     const float* __restrict__ Wq, const float* __restrict__ bq,
                     const float* __restrict__ Wk, const float* __restrict__ bk,
                     float* __restrict__ Qout, float* __restrict__ Kout) {
    extern __shared__ float sm[];
    float* As = sm;                        // [2][128][SA]
    float* Bs = sm + 2 * TILE_FLOATS;      // [2][128][SA]

    const int tid  = threadIdx.x;
    const int wid  = tid >> 5;
    const int lane = tid & 31;
    const int wm   = wid >> 2;             // 0..1
    const int wn   = wid & 3;              // 0..3
    const int gq   = lane >> 2;            // 0..7
    const int tg   = lane & 3;             // 0..3

    const float* W    = blockIdx.z ? Wk : Wq;
    const float* bias = blockIdx.z ? bk : bq;
    float*       C    = blockIdx.z ? Kout : Qout;
    const int m0 = blockIdx.x * BM;
    const int n0 = blockIdx.y * BN;

    const uint32_t uA = smem_u32(As);
    const uint32_t uB = smem_u32(Bs);

    float acc[4][4][4];
    #pragma unroll
    for (int i = 0; i < 4; i++)
        #pragma unroll
        for (int j = 0; j < 4; j++)
            #pragma unroll
            for (int k = 0; k < 4; k++) acc[i][j][k] = 0.f;

    // per-thread load slots: 4 chunks of 16B per tile
    const int lrow = tid >> 3;             // 0..31 (base row, +32 per i)
    const int lc8  = tid & 7;              // float4 index within the 32-float row

    auto load_stage = [&](int k0, int s) {
        const uint32_t a_off = (uint32_t)(s * TILE_FLOATS) * 4;
        const uint32_t b_off = a_off;
        #pragma unroll
        for (int i = 0; i < 4; i++) {
            int row = lrow + i * 32;
            cp16(uA + a_off + (uint32_t)(row * SA + lc8 * 4) * 4,
                 x + (size_t)(m0 + row) * EMB + k0 + lc8 * 4);
        }
        #pragma unroll
        for (int i = 0; i < 4; i++) {
            int row = lrow + i * 32;
            cp16(uB + b_off + (uint32_t)(row * SA + lc8 * 4) * 4,
                 W + (size_t)(n0 + row) * EMB + k0 + lc8 * 4);
        }
    };

    load_stage(0, 0);
    cp_commit();

    #pragma unroll 1
    for (int c = 0; c < NKITER; c++) {
        const int cur = c & 1;
        if (c + 1 < NKITER) {
            load_stage((c + 1) * BK, cur ^ 1);
            cp_commit();
            cp_wait<1>();
        } else {
            cp_wait<0>();
        }
        __syncthreads();

        const float* Ab = As + cur * TILE_FLOATS;
        const float* Bb = Bs + cur * TILE_FLOATS;

        #pragma unroll
        for (int ks = 0; ks < 4; ks++) {
            const int kb = ks * 8;
            uint32_t af[4][4];
            #pragma unroll
            for (int mt = 0; mt < 4; mt++) {
                const int r = wm * 64 + mt * 16 + gq;
                af[mt][0] = f2tf32(Ab[(size_t)r * SA + kb + tg]);
                af[mt][1] = f2tf32(Ab[(size_t)(r + 8) * SA + kb + tg]);
                af[mt][2] = f2tf32(Ab[(size_t)r * SA + kb + tg + 4]);
                af[mt][3] = f2tf32(Ab[(size_t)(r + 8) * SA + kb + tg + 4]);
            }
            uint32_t bf[4][2];
            #pragma unroll
            for (int nt = 0; nt < 4; nt++) {
                const int n = wn * 32 + nt * 8 + gq;
                bf[nt][0] = f2tf32(Bb[(size_t)n * SA + kb + tg]);
                bf[nt][1] = f2tf32(Bb[(size_t)n * SA + kb + tg + 4]);
            }
            #pragma unroll
            for (int mt = 0; mt < 4; mt++)
                #pragma unroll
                for (int nt = 0; nt < 4; nt++)
                    mma_tf32(acc[mt][nt], af[mt], bf[nt]);
        }
        __syncthreads();
    }

    // epilogue: bias add + float2 stores
    #pragma unroll
    for (int mt = 0; mt < 4; mt++) {
        const int r = m0 + wm * 64 + mt * 16 + gq;
        #pragma unroll
        for (int nt = 0; nt < 4; nt++) {
            const int cn = n0 + wn * 32 + nt * 8 + tg * 2;
            const float2 bb = *(const float2*)(bias + cn);
            float2 v0, v1;
            v0.x = acc[mt][nt][0] + bb.x; v0.y = acc[mt][nt][1] + bb.y;
            v1.x = acc[mt][nt][2] + bb.x; v1.y = acc[mt][nt][3] + bb.y;
            *(float2*)(C + (size_t)r * EMB + cn)       = v0;
            *(float2*)(C + (size_t)(r + 8) * EMB + cn) = v1;
        }
    }
}

// ---------------- partial sums of x over n -----------------------------------
__global__ __launch_bounds__(256)
void xpart_kernel(const float* __restrict__ x, float* __restrict__ xpart) {
    const int b = blockIdx.x;                 // 0..1
    const int c = blockIdx.y;                 // 0..63 (32-row chunk)
    const int t = threadIdx.x;
    const size_t base = (size_t)b * N_SEQ * EMB + (size_t)c * 32 * EMB;
    float s0 = 0.f, s1 = 0.f;
    for (int n = 0; n < 32; n++) {
        s0 += x[base + (size_t)n * EMB + t];
        s1 += x[base + (size_t)n * EMB + t + 256];
    }
    xpart[(size_t)(b * 64 + c) * EMB + t]       = s0;
    xpart[(size_t)(b * 64 + c) * EMB + t + 256] = s1;
}

// ---------------- basis: Vsum (j=0) and V rows 0..2 (j=1..3) ------------------
__global__ __launch_bounds__(256)
void basis_kernel(const float* __restrict__ x, const float* __restrict__ xpart,
                  const float* __restrict__ Wv, const float* __restrict__ bv,
                  float* __restrict__ basis) {
    const int b = blockIdx.x;     // 0..1
    const int j = blockIdx.y;     // 0..3
    const int eo0 = blockIdx.z * 64;
    const int t = threadIdx.x;
    const int w = t >> 5, lane = t & 31;
    __shared__ float vec[EMB];

    if (j == 0) {
        float s0 = 0.f, s1 = 0.f;
        for (int c = 0; c < 64; c++) {
            s0 += xpart[(size_t)(b * 64 + c) * EMB + t];
            s1 += xpart[(size_t)(b * 64 + c) * EMB + t + 256];
        }
        vec[t] = s0; vec[t + 256] = s1;
    } else {
        const size_t rb = ((size_t)b * N_SEQ + (j - 1)) * EMB;
        vec[t] = x[rb + t];
        vec[t + 256] = x[rb + t + 256];
    }
    __syncthreads();

    const float bscale = (j == 0) ? (float)N_SEQ : 1.f;
    #pragma unroll
    for (int i = 0; i < 8; i++) {
        const int eo = eo0 + w * 8 + i;
        const float4* wr = (const float4*)(Wv + (size_t)eo * EMB);
        const float4* vr = (const float4*)vec;
        float acc = 0.f;
        #pragma unroll
        for (int ii = 0; ii < 4; ii++) {
            float4 wv = wr[lane + 32 * ii];
            float4 vv = vr[lane + 32 * ii];
            acc += wv.x * vv.x + wv.y * vv.y + wv.z * vv.z + wv.w * vv.w;
        }
        #pragma unroll
        for (int off = 16; off; off >>= 1)
            acc += __shfl_xor_sync(0xffffffff, acc, off);
        if (lane == 0)
            basis[(size_t)(b * 4 + j) * EMB + eo] = acc + bv[eo] * bscale;
    }
}

// ---------------- U[b][h][j][e] = sum_d basis[b][j][h*64+d] * Wo[e][h*64+d] --
__global__ __launch_bounds__(256)
void u_kernel(const float* __restrict__ basis, const float* __restrict__ Wo,
              float* __restrict__ U) {
    const int bh = blockIdx.x;          // 0..15
    const int b = bh >> 3, h = bh & 7;
    const int eo0 = blockIdx.y * 128;   // 4 slices
    const int t = threadIdx.x;
    const int w = t >> 5, lane = t & 31;
    __shared__ float bs[4][HD];
    {
        const int j = t >> 6, d = t & 63;
        bs[j][d] = basis[(size_t)(b * 4 + j) * EMB + h * HD + d];
    }
    __syncthreads();

    #pragma unroll
    for (int i = 0; i < 16; i++) {
        const int eo = eo0 + w * 16 + i;
        const float w0 = Wo[(size_t)eo * EMB + h * HD + lane];
        const float w1 = Wo[(size_t)eo * EMB + h * HD + lane + 32];
        #pragma unroll
        for (int j = 0; j < 4; j++) {
            float d = w0 * bs[j][lane] + w1 * bs[j][lane + 32];
            #pragma unroll
            for (int off = 16; off; off >>= 1)
                d += __shfl_xor_sync(0xffffffff, d, off);
            if (lane == 0)
                U[((size_t)(b * NHEAD + h) * 4 + j) * EMB + eo] = d;
        }
    }
}

// ---------------- coefficients ------------------------------------------------
__global__ __launch_bounds__(256)
void coef_kernel(const float* __restrict__ Q, const float* __restrict__ K,
                 float* __restrict__ coef) {
    const int bh = blockIdx.x;                  // 0..15
    const int b = bh >> 3, h = bh & 7;
    const int r0 = blockIdx.y * 64;
    const int warp = threadIdx.x >> 5;
    const int lane = threadIdx.x & 31;
    const size_t base = (size_t)b * N_SEQ * EMB + h * HD;

    for (int rr = warp; rr < 64; rr += 8) {
        const int r = r0 + rr;
        const float* qp = Q + base + (size_t)r * EMB;
        const float q0 = qp[lane];
        const float q1 = qp[lane + 32];

        float e[3];
        #pragma unroll
        for (int c = 0; c < 3; c++) {
            const int kr = r + c - 1;
            const bool valid = (kr >= 0 && kr < N_SEQ);
            float v = 0.f;
            if (valid) {
                const float* kp = K + base + (size_t)kr * EMB;
                v = q0 * kp[lane] + q1 * kp[lane + 32];
            }
            #pragma unroll
            for (int off = 16; off; off >>= 1)
                v += __shfl_xor_sync(0xffffffff, v, off);
            e[c] = valid ? (expf(v) - 1.f) : 0.f;
        }

        const float inv = 1.f / ((float)N_SEQ + e[0] + e[1] + e[2]);
        if (lane < 4) {
            const float val = (lane == 0) ? inv : inv * e[lane - 1];
            coef[((size_t)(b * N_SEQ + r) * NHEAD + h) * 4 + lane] = val;
        }
    }
}

// ---------------- out[b,r,:] = bo + sum_{h,j} coef * U -------------------------
__global__ __launch_bounds__(256)
void out_kernel(const float* __restrict__ U, const float* __restrict__ coef,
                const float* __restrict__ bo, float* __restrict__ out) {
    const int blk = blockIdx.x;                 // 0..255
    const int b = blk >> 7;
    const int r0 = (blk & 127) * 16;
    const int t = threadIdx.x;

    float u0[32], u1[32];
    #pragma unroll
    for (int hj = 0; hj < 32; hj++) {
        u0[hj] = U[((size_t)b * 32 + hj) * EMB + t];
        u1[hj] = U[((size_t)b * 32 + hj) * EMB + t + 256];
    }
    const float bo0 = bo[t], bo1 = bo[t + 256];

    __shared__ float sc[16][32];
    {
        const size_t cb = (size_t)(b * N_SEQ + r0) * 32;
        int i0 = t;        sc[i0 / 32][i0 % 32] = coef[cb + i0];
        int i1 = t + 256;  sc[i1 / 32][i1 % 32] = coef[cb + i1];
    }
    __syncthreads();

    for (int rr = 0; rr < 16; rr++) {
        float a0 = bo0, a1 = bo1;
        #pragma unroll
        for (int hj = 0; hj < 32; hj++) {
            const float c = sc[rr][hj];
            a0 = fmaf(c, u0[hj], a0);
            a1 = fmaf(c, u1[hj], a1);
        }
        const size_t ob = (size_t)(b * N_SEQ + r0 + rr) * EMB;
        out[ob + t]       = a0;
        out[ob + t + 256] = a1;
    }
}

// ---------------- launch --------------------------------------------------------
extern "C" void kernel_launch(void* const* d_in, const int* in_sizes, int n_in,
                              void* d_out, int out_size) {
    const float* x  = (const float*)d_in[0];
    const float* Wq = (const float*)d_in[1];
    const float* bq = (const float*)d_in[2];
    const float* Wk = (const float*)d_in[3];
    const float* bk = (const float*)d_in[4];
    const float* Wv = (const float*)d_in[5];
    const float* bv = (const float*)d_in[6];
    const float* Wo = (const float*)d_in[7];
    const float* bo = (const float*)d_in[8];
    float* outp = (float*)d_out;

    float *Qp, *Kp, *xpp, *bsp, *Up, *cfp;
    cudaGetSymbolAddress((void**)&Qp,  g_Q);
    cudaGetSymbolAddress((void**)&Kp,  g_K);
    cudaGetSymbolAddress((void**)&xpp, g_xpart);
    cudaGetSymbolAddress((void**)&bsp, g_basis);
    cudaGetSymbolAddress((void**)&Up,  g_U);
    cudaGetSymbolAddress((void**)&cfp, g_coef);

    cudaFuncSetAttribute(qk_gemm_tf32mma,
                         cudaFuncAttributeMaxDynamicSharedMemorySize, GEMM_SMEM);

    // heavy GEMM first (tensor cores via mma.sync tf32)
    qk_gemm_tf32mma<<<dim3(M_ROWS / BM, EMB / BN, 2), 256, GEMM_SMEM>>>(
        x, Wq, bq, Wk, bk, Qp, Kp);

    // prep chain for the value/output path
    xpart_kernel<<<dim3(BATCH, 64), 256>>>(x, xpp);
    basis_kernel<<<dim3(BATCH, 4, 8), 256>>>(x, xpp, Wv, bv, bsp);
    u_kernel<<<dim3(BATCH * NHEAD, 4), 256>>>(bsp, Wo, Up);

    coef_kernel<<<dim3(BATCH * NHEAD, 32), 256>>>(Qp, Kp, cfp);
    out_kernel<<<256, 256>>>(Up, cfp, bo, outp);
}

// round 9
// speedup vs baseline: 5.3134x; 1.0351x over previous
#include <cuda_runtime.h>
#include <cuda_fp16.h>
#include <math.h>
#include <stdint.h>

// Problem constants
#define BATCH   2
#define N_SEQ   2048
#define EMB     512
#define NHEAD   8
#define HD      64
#define M_ROWS  (BATCH * N_SEQ)   // 4096

// ---------------- scratch ----------------------------------------------------
__device__ __half g_xh[M_ROWS * EMB];
__device__ __half g_wqh[EMB * EMB];
__device__ __half g_wkh[EMB * EMB];
__device__ float  g_Q[M_ROWS * EMB];
__device__ float  g_K[M_ROWS * EMB];
__device__ float  g_xpart[BATCH * 64 * EMB];
__device__ float  g_U[BATCH * NHEAD * 4 * EMB];

// ---------------- helpers ------------------------------------------------------
__device__ __forceinline__ uint32_t smem_u32(const void* p) {
    uint32_t a;
    asm("{ .reg .u64 t; cvta.to.shared.u64 t, %1; cvt.u32.u64 %0, t; }"
        : "=r"(a) : "l"(p));
    return a;
}

__device__ __forceinline__ void cp16(uint32_t dst, const void* src) {
    asm volatile("cp.async.cg.shared.global [%0], [%1], 16;"
                 :: "r"(dst), "l"(src) : "memory");
}
__device__ __forceinline__ void cp_commit() {
    asm volatile("cp.async.commit_group;" ::: "memory");
}
template <int N> __device__ __forceinline__ void cp_wait() {
    asm volatile("cp.async.wait_group %0;" :: "n"(N) : "memory");
}

__device__ __forceinline__ void mma_f16(float d[4], const uint32_t a[4],
                                        const uint32_t b[2]) {
    asm volatile(
        "mma.sync.aligned.m16n8k16.row.col.f32.f16.f16.f32 "
        "{%0,%1,%2,%3}, {%4,%5,%6,%7}, {%8,%9}, {%0,%1,%2,%3};"
        : "+f"(d[0]), "+f"(d[1]), "+f"(d[2]), "+f"(d[3])
        : "r"(a[0]), "r"(a[1]), "r"(a[2]), "r"(a[3]), "r"(b[0]), "r"(b[1]));
}

// ---------------- fp32 -> fp16 pre-convert ------------------------------------
#define PH_X_F4 (M_ROWS * EMB / 4)   // 524288
#define PH_W_F4 (EMB * EMB / 4)      // 65536

__global__ __launch_bounds__(256)
void prep_half(const float* __restrict__ x, const float* __restrict__ Wq,
               const float* __restrict__ Wk, __half* __restrict__ xh,
               __half* __restrict__ wqh, __half* __restrict__ wkh) {
    const int total = PH_X_F4 + 2 * PH_W_F4;
    for (int i = blockIdx.x * blockDim.x + threadIdx.x; i < total;
         i += gridDim.x * blockDim.x) {
        const float4* src;
        __half2* dst;
        int off;
        if (i < PH_X_F4)                { src = (const float4*)x;  dst = (__half2*)xh;  off = i; }
        else if (i < PH_X_F4 + PH_W_F4) { src = (const float4*)Wq; dst = (__half2*)wqh; off = i - PH_X_F4; }
        else                            { src = (const float4*)Wk; dst = (__half2*)wkh; off = i - PH_X_F4 - PH_W_F4; }
        float4 v = src[off];
        dst[off * 2]     = __floats2half2_rn(v.x, v.y);
        dst[off * 2 + 1] = __floats2half2_rn(v.z, v.w);
    }
}

// ---------------- fp16 mma.sync GEMM: Q,K = X @ W.T + b ------------------------
// CTA tile 128x128, BK=64 halves, 8 warps (2x4), warp tile 64x32, 2 stages.
#define BKH 64
#define SAH 72                        // padded row stride in halves
#define TILE_HALVES (128 * SAH)       // 9216
#define TILE_BYTES  (TILE_HALVES * 2) // 18432
#define NKIT (EMB / BKH)              // 8
#define GEMM_SMEM (4 * TILE_BYTES)    // 73728

__global__ __launch_bounds__(256, 2)
void qk_gemm_f16(const __half* __restrict__ xh,
                 const __half* __restrict__ wqh, const float* __restrict__ bq,
                 const __half* __restrict__ wkh, const float* __restrict__ bk,
                 float* __restrict__ Qout, float* __restrict__ Kout) {
    extern __shared__ __half smh[];
    const int tid  = threadIdx.x;
    const int wid  = tid >> 5;
    const int lane = tid & 31;
    const int wm   = wid >> 2;
    const int wn   = wid & 3;
    const int g    = lane >> 2;
    const int tg   = lane & 3;

    const __half* W    = blockIdx.z ? wkh : wqh;
    const float*  bias = blockIdx.z ? bk  : bq;
    float*        C    = blockIdx.z ? Kout : Qout;
    const int m0 = blockIdx.x * 128;
    const int n0 = blockIdx.y * 128;

    const uint32_t uS = smem_u32(smh);

    float acc[4][4][4];
    #pragma unroll
    for (int i = 0; i < 4; i++)
        #pragma unroll
        for (int j = 0; j < 4; j++)
            #pragma unroll
            for (int k = 0; k < 4; k++) acc[i][j][k] = 0.f;

    const int lrow = tid >> 1;          // 0..127
    const int lcb  = (tid & 1) * 4;     // chunk base 0 or 4

    auto load_stage = [&](int k0, int s) {
        const uint32_t a_base = uS + (uint32_t)s * TILE_BYTES;
        const uint32_t b_base = uS + (uint32_t)(2 + s) * TILE_BYTES;
        #pragma unroll
        for (int i = 0; i < 4; i++) {
            const int ch = lcb + i;
            cp16(a_base + (uint32_t)(lrow * SAH + ch * 8) * 2,
                 xh + (size_t)(m0 + lrow) * EMB + k0 + ch * 8);
            cp16(b_base + (uint32_t)(lrow * SAH + ch * 8) * 2,
                 W + (size_t)(n0 + lrow) * EMB + k0 + ch * 8);
        }
    };

    load_stage(0, 0);
    cp_commit();

    #pragma unroll 1
    for (int c = 0; c < NKIT; c++) {
        const int cur = c & 1;
        if (c + 1 < NKIT) {
            load_stage((c + 1) * BKH, cur ^ 1);
            cp_commit();
            cp_wait<1>();
        } else {
            cp_wait<0>();
        }
        __syncthreads();

        const __half* Ah = smh + (size_t)cur * TILE_HALVES;
        const __half* Bh = smh + (size_t)(2 + cur) * TILE_HALVES;

        #pragma unroll
        for (int ks = 0; ks < 4; ks++) {
            uint32_t af[4][4], bf[4][2];
            #pragma unroll
            for (int mt = 0; mt < 4; mt++) {
                const int r = wm * 64 + mt * 16 + g;
                const __half* ap = Ah + r * SAH + ks * 16 + tg * 2;
                af[mt][0] = *(const uint32_t*)(ap);
                af[mt][1] = *(const uint32_t*)(ap + 8 * SAH);
                af[mt][2] = *(const uint32_t*)(ap + 8);
                af[mt][3] = *(const uint32_t*)(ap + 8 * SAH + 8);
            }
            #pragma unroll
            for (int nt = 0; nt < 4; nt++) {
                const int n = wn * 32 + nt * 8 + g;
                const __half* bp = Bh + n * SAH + ks * 16 + tg * 2;
                bf[nt][0] = *(const uint32_t*)(bp);
                bf[nt][1] = *(const uint32_t*)(bp + 8);
            }
            #pragma unroll
            for (int mt = 0; mt < 4; mt++)
                #pragma unroll
                for (int nt = 0; nt < 4; nt++)
                    mma_f16(acc[mt][nt], af[mt], bf[nt]);
        }
        __syncthreads();
    }

    // epilogue: bias add + float2 stores
    #pragma unroll
    for (int mt = 0; mt < 4; mt++) {
        const int r = m0 + wm * 64 + mt * 16 + g;
        #pragma unroll
        for (int nt = 0; nt < 4; nt++) {
            const int cn = n0 + wn * 32 + nt * 8 + tg * 2;
            const float2 bb = *(const float2*)(bias + cn);
            float2 v0, v1;
            v0.x = acc[mt][nt][0] + bb.x; v0.y = acc[mt][nt][1] + bb.y;
            v1.x = acc[mt][nt][2] + bb.x; v1.y = acc[mt][nt][3] + bb.y;
            *(float2*)(C + (size_t)r * EMB + cn)       = v0;
            *(float2*)(C + (size_t)(r + 8) * EMB + cn) = v1;
        }
    }
}

// ---------------- partial sums of x over n (64 partials per batch) ------------
__global__ __launch_bounds__(256)
void xpart_kernel(const float* __restrict__ x, float* __restrict__ xpart) {
    __shared__ float4 stage[128];
    const int b = blockIdx.x;                 // 0..1
    const int c = blockIdx.y;                 // 0..63 (32-row chunk)
    const int t = threadIdx.x;
    const int fc = t & 127;                   // float4 column
    const int half = t >> 7;                  // 0/1

    const float4* base = (const float4*)(x + ((size_t)b * N_SEQ + c * 32 + half * 16) * EMB);
    float4 s = make_float4(0.f, 0.f, 0.f, 0.f);
    #pragma unroll 4
    for (int n = 0; n < 16; n++) {
        float4 v = base[(size_t)n * (EMB / 4) + fc];
        s.x += v.x; s.y += v.y; s.z += v.z; s.w += v.w;
    }
    if (half == 1) stage[fc] = s;
    __syncthreads();
    if (half == 0) {
        float4 o = stage[fc];
        o.x += s.x; o.y += s.y; o.z += s.z; o.w += s.w;
        *(float4*)(xpart + ((size_t)b * 64 + c) * EMB + fc * 4) = o;
    }
}

// ---------------- fused basis + U ----------------------------------------------
// Block (b,h): bs[j][d] = dot(Wv[h*64+d], vec_j) + bv*scale; then
// U[b][h][j][eo] = dot(Wo[eo][h*64:...+64], bs[j])
#define BU_SMEM ((4 * EMB + 4 * HD + 256 * 65) * 4)   // 75776 B

__global__ __launch_bounds__(256)
void basis_u_kernel(const float* __restrict__ x, const float* __restrict__ xpart,
                    const float* __restrict__ Wv, const float* __restrict__ bv,
                    const float* __restrict__ Wo, float* __restrict__ U) {
    extern __shared__ float smb[];
    float* vec = smb;                   // [4][512]
    float* bs  = smb + 4 * EMB;         // [4][64]
    float* sWo = smb + 4 * EMB + 4 * HD; // [256][65]

    const int bh = blockIdx.x;          // 0..15
    const int b = bh >> 3, h = bh & 7;
    const int t = threadIdx.x;
    const int w = t >> 5, lane = t & 31;

    // vec0 = xsum (reduce 64 partials); vec1..3 = x rows 0..2
    if (t < 128) {
        const float4* xp = (const float4*)(xpart + (size_t)b * 64 * EMB) + t;
        float4 s = make_float4(0.f, 0.f, 0.f, 0.f);
        #pragma unroll 4
        for (int r = 0; r < 64; r++) {
            float4 v = xp[(size_t)r * (EMB / 4)];
            s.x += v.x; s.y += v.y; s.z += v.z; s.w += v.w;
        }
        *(float4*)(vec + t * 4) = s;
    } else {
        const int fc = t - 128;         // 0..127
        #pragma unroll
        for (int j = 1; j < 4; j++) {
            float4 v = *(const float4*)(x + ((size_t)b * N_SEQ + (j - 1)) * EMB + fc * 4);
            *(float4*)(vec + j * EMB + fc * 4) = v;
        }
    }
    __syncthreads();

    // Phase A: warp w handles d = w*8 .. w*8+7
    #pragma unroll
    for (int dd = 0; dd < 8; dd++) {
        const int d = w * 8 + dd;
        const float4* wr = (const float4*)(Wv + (size_t)(h * HD + d) * EMB);
        float4 wv[4];
        #pragma unroll
        for (int i = 0; i < 4; i++) wv[i] = wr[lane + 32 * i];
        float a[4];
        #pragma unroll
        for (int j = 0; j < 4; j++) {
            const float4* vr = (const float4*)(vec + j * EMB);
            float s = 0.f;
            #pragma unroll
            for (int i = 0; i < 4; i++) {
                float4 vv = vr[lane + 32 * i];
                s += wv[i].x * vv.x + wv[i].y * vv.y + wv[i].z * vv.z + wv[i].w * vv.w;
            }
            a[j] = s;
        }
        #pragma unroll
        for (int off = 16; off; off >>= 1)
            #pragma unroll
            for (int j = 0; j < 4; j++)
                a[j] += __shfl_xor_sync(0xffffffff, a[j], off);
        if (lane < 4) {
            const int j = lane;
            const float scale = (j == 0) ? (float)N_SEQ : 1.f;
            bs[j * HD + d] = a[j] + bv[h * HD + d] * scale;
        }
    }
    __syncthreads();

    // Phase B: two chunks of 256 eo
    for (int ch = 0; ch < 2; ch++) {
        const int eo0 = ch * 256;
        // load Wo slice [256][64] into padded smem
        #pragma unroll
        for (int i = 0; i < 16; i++) {
            const int fi = t + 256 * i;        // f4 index over 4096
            const int r = fi >> 4, c4 = fi & 15;
            float4 v = *(const float4*)(Wo + (size_t)(eo0 + r) * EMB + h * HD + c4 * 4);
            float* dst = sWo + r * 65 + c4 * 4;
            dst[0] = v.x; dst[1] = v.y; dst[2] = v.z; dst[3] = v.w;
        }
        __syncthreads();

        float a[4] = {0.f, 0.f, 0.f, 0.f};
        const float* wrow = sWo + t * 65;
        #pragma unroll 8
        for (int d = 0; d < HD; d++) {
            const float wv = wrow[d];
            #pragma unroll
            for (int j = 0; j < 4; j++)
                a[j] = fmaf(wv, bs[j * HD + d], a[j]);
        }
        #pragma unroll
        for (int j = 0; j < 4; j++)
            U[((size_t)(b * NHEAD + h) * 4 + j) * EMB + eo0 + t] = a[j];
        __syncthreads();
    }
}

// ---------------- fused coef + out ----------------------------------------------
// Block = (b, 16-row group). Warp h computes the 3 windowed dots + exp for its
// head; then all threads combine: out = bo + sum_{h,j} coef * U.
__global__ __launch_bounds__(256)
void coef_out_kernel(const float* __restrict__ Q, const float* __restrict__ K,
                     const float* __restrict__ U, const float* __restrict__ bo,
                     float* __restrict__ out) {
    const int blk = blockIdx.x;                 // 0..255
    const int b = blk >> 7;
    const int r0 = (blk & 127) * 16;
    const int t = threadIdx.x;
    const int h = t >> 5;                       // warp = head
    const int lane = t & 31;

    // phase 0: U columns for this thread (coalesced)
    float u0[32], u1[32];
    #pragma unroll
    for (int hj = 0; hj < 32; hj++) {
        u0[hj] = U[((size_t)b * 32 + hj) * EMB + t];
        u1[hj] = U[((size_t)b * 32 + hj) * EMB + t + 256];
    }

    // phase 1: coefficients
    __shared__ float sc[16][32];
    const size_t base = (size_t)b * N_SEQ * EMB + h * HD;
    #pragma unroll 2
    for (int rr = 0; rr < 16; rr++) {
        const int r = r0 + rr;
        const float q0 = Q[base + (size_t)r * EMB + lane];
        const float q1 = Q[base + (size_t)r * EMB + lane + 32];
        float v[3];
        bool valid[3];
        #pragma unroll
        for (int c = 0; c < 3; c++) {
            const int kr = r + c - 1;
            valid[c] = (kr >= 0 && kr < N_SEQ);
            if (valid[c]) {
                const float* kp = K + base + (size_t)kr * EMB;
                v[c] = q0 * kp[lane] + q1 * kp[lane + 32];
            } else v[c] = 0.f;
        }
        #pragma unroll
        for (int off = 16; off; off >>= 1)
            #pragma unroll
            for (int c = 0; c < 3; c++)
                v[c] += __shfl_xor_sync(0xffffffff, v[c], off);
        float e[3];
        #pragma unroll
        for (int c = 0; c < 3; c++)
            e[c] = valid[c] ? (expf(v[c]) - 1.f) : 0.f;
        const float inv = 1.f / ((float)N_SEQ + e[0] + e[1] + e[2]);
        if (lane < 4)
            sc[rr][h * 4 + lane] = (lane == 0) ? inv : inv * e[lane - 1];
    }
    __syncthreads();

    // phase 2: combine
    const float bo0 = bo[t], bo1 = bo[t + 256];
    #pragma unroll 2
    for (int rr = 0; rr < 16; rr++) {
        float a0 = bo0, a1 = bo1;
        #pragma unroll
        for (int hj = 0; hj < 32; hj++) {
            const float c = sc[rr][hj];
            a0 = fmaf(c, u0[hj], a0);
            a1 = fmaf(c, u1[hj], a1);
        }
        const size_t ob = ((size_t)b * N_SEQ + r0 + rr) * EMB;
        out[ob + t]       = a0;
        out[ob + t + 256] = a1;
    }
}

// ---------------- launch ----------------------------------------------------------
extern "C" void kernel_launch(void* const* d_in, const int* in_sizes, int n_in,
                              void* d_out, int out_size) {
    const float* x  = (const float*)d_in[0];
    const float* Wq = (const float*)d_in[1];
    const float* bq = (const float*)d_in[2];
    const float* Wk = (const float*)d_in[3];
    const float* bk = (const float*)d_in[4];
    const float* Wv = (const float*)d_in[5];
    const float* bv = (const float*)d_in[6];
    const float* Wo = (const float*)d_in[7];
    const float* bo = (const float*)d_in[8];
    float* outp = (float*)d_out;

    __half *xh, *wqh, *wkh;
    float *Qp, *Kp, *xpp, *Up;
    cudaGetSymbolAddress((void**)&xh,  g_xh);
    cudaGetSymbolAddress((void**)&wqh, g_wqh);
    cudaGetSymbolAddress((void**)&wkh, g_wkh);
    cudaGetSymbolAddress((void**)&Qp,  g_Q);
    cudaGetSymbolAddress((void**)&Kp,  g_K);
    cudaGetSymbolAddress((void**)&xpp, g_xpart);
    cudaGetSymbolAddress((void**)&Up,  g_U);

    cudaFuncSetAttribute(qk_gemm_f16,
                         cudaFuncAttributeMaxDynamicSharedMemorySize, GEMM_SMEM);
    cudaFuncSetAttribute(basis_u_kernel,
                         cudaFuncAttributeMaxDynamicSharedMemorySize, BU_SMEM);

    prep_half<<<640, 256>>>(x, Wq, Wk, xh, wqh, wkh);

    qk_gemm_f16<<<dim3(M_ROWS / 128, EMB / 128, 2), 256, GEMM_SMEM>>>(
        xh, wqh, bq, wkh, bk, Qp, Kp);

    xpart_kernel<<<dim3(BATCH, 64), 256>>>(x, xpp);
    basis_u_kernel<<<BATCH * NHEAD, 256, BU_SMEM>>>(x, xpp, Wv, bv, Wo, Up);

    coef_out_kernel<<<256, 256>>>(Qp, Kp, Up, bo, outp);
}

// round 11
// speedup vs baseline: 5.8023x; 1.0920x over previous
#include <cuda_runtime.h>
#include <cuda_fp16.h>
#include <math.h>
#include <stdint.h>

// Problem constants
#define BATCH   2
#define N_SEQ   2048
#define EMB     512
#define NHEAD   8
#define HD      64
#define M_ROWS  (BATCH * N_SEQ)   // 4096

// ---------------- scratch ----------------------------------------------------
__device__ __half g_xh[M_ROWS * EMB];
__device__ __half g_wqh[EMB * EMB];
__device__ __half g_wkh[EMB * EMB];
__device__ __half g_Qh[M_ROWS * EMB];
__device__ __half g_Kh[M_ROWS * EMB];
__device__ float  g_xpart[BATCH * 16 * EMB];
__device__ float  g_bs[BATCH * 4 * EMB];          // [b][j][row(=h*64+d)]
__device__ float  g_U[BATCH * NHEAD * 4 * EMB];

// ---------------- helpers ------------------------------------------------------
__device__ __forceinline__ uint32_t smem_u32(const void* p) {
    uint32_t a;
    asm("{ .reg .u64 t; cvta.to.shared.u64 t, %1; cvt.u32.u64 %0, t; }"
        : "=r"(a) : "l"(p));
    return a;
}

__device__ __forceinline__ void cp16(uint32_t dst, const void* src) {
    asm volatile("cp.async.cg.shared.global [%0], [%1], 16;"
                 :: "r"(dst), "l"(src) : "memory");
}
__device__ __forceinline__ void cp_commit() {
    asm volatile("cp.async.commit_group;" ::: "memory");
}
template <int N> __device__ __forceinline__ void cp_wait() {
    asm volatile("cp.async.wait_group %0;" :: "n"(N) : "memory");
}

__device__ __forceinline__ void mma_f16(float d[4], const uint32_t a[4],
                                        const uint32_t b[2]) {
    asm volatile(
        "mma.sync.aligned.m16n8k16.row.col.f32.f16.f16.f32 "
        "{%0,%1,%2,%3}, {%4,%5,%6,%7}, {%8,%9}, {%0,%1,%2,%3};"
        : "+f"(d[0]), "+f"(d[1]), "+f"(d[2]), "+f"(d[3])
        : "r"(a[0]), "r"(a[1]), "r"(a[2]), "r"(a[3]), "r"(b[0]), "r"(b[1]));
}

// ---------------- fp32 -> fp16 pre-convert ------------------------------------
#define PH_X_F4 (M_ROWS * EMB / 4)   // 524288
#define PH_W_F4 (EMB * EMB / 4)      // 65536

__global__ __launch_bounds__(256)
void prep_half(const float* __restrict__ x, const float* __restrict__ Wq,
               const float* __restrict__ Wk, __half* __restrict__ xh,
               __half* __restrict__ wqh, __half* __restrict__ wkh) {
    const int total = PH_X_F4 + 2 * PH_W_F4;
    for (int i = blockIdx.x * blockDim.x + threadIdx.x; i < total;
         i += gridDim.x * blockDim.x) {
        const float4* src;
        __half2* dst;
        int off;
        if (i < PH_X_F4)                { src = (const float4*)x;  dst = (__half2*)xh;  off = i; }
        else if (i < PH_X_F4 + PH_W_F4) { src = (const float4*)Wq; dst = (__half2*)wqh; off = i - PH_X_F4; }
        else                            { src = (const float4*)Wk; dst = (__half2*)wkh; off = i - PH_X_F4 - PH_W_F4; }
        float4 v = src[off];
        dst[off * 2]     = __floats2half2_rn(v.x, v.y);
        dst[off * 2 + 1] = __floats2half2_rn(v.z, v.w);
    }
}

// ---------------- fp16 mma.sync GEMM: Q,K = X @ W.T + b (fp16 out) -------------
#define BKH 64
#define SAH 72                        // padded row stride in halves
#define TILE_HALVES (128 * SAH)       // 9216
#define TILE_BYTES  (TILE_HALVES * 2) // 18432
#define NKIT (EMB / BKH)              // 8
#define GEMM_SMEM (4 * TILE_BYTES)    // 73728

__global__ __launch_bounds__(256, 2)
void qk_gemm_f16(const __half* __restrict__ xh,
                 const __half* __restrict__ wqh, const float* __restrict__ bq,
                 const __half* __restrict__ wkh, const float* __restrict__ bk,
                 __half* __restrict__ Qout, __half* __restrict__ Kout) {
    extern __shared__ __half smh[];
    const int tid  = threadIdx.x;
    const int wid  = tid >> 5;
    const int lane = tid & 31;
    const int wm   = wid >> 2;
    const int wn   = wid & 3;
    const int g    = lane >> 2;
    const int tg   = lane & 3;

    const __half* W    = blockIdx.z ? wkh : wqh;
    const float*  bias = blockIdx.z ? bk  : bq;
    __half*       C    = blockIdx.z ? Kout : Qout;
    const int m0 = blockIdx.x * 128;
    const int n0 = blockIdx.y * 128;

    const uint32_t uS = smem_u32(smh);

    float acc[4][4][4];
    #pragma unroll
    for (int i = 0; i < 4; i++)
        #pragma unroll
        for (int j = 0; j < 4; j++)
            #pragma unroll
            for (int k = 0; k < 4; k++) acc[i][j][k] = 0.f;

    const int lrow = tid >> 1;          // 0..127
    const int lcb  = (tid & 1) * 4;     // chunk base 0 or 4

    auto load_stage = [&](int k0, int s) {
        const uint32_t a_base = uS + (uint32_t)s * TILE_BYTES;
        const uint32_t b_base = uS + (uint32_t)(2 + s) * TILE_BYTES;
        #pragma unroll
        for (int i = 0; i < 4; i++) {
            const int ch = lcb + i;
            cp16(a_base + (uint32_t)(lrow * SAH + ch * 8) * 2,
                 xh + (size_t)(m0 + lrow) * EMB + k0 + ch * 8);
            cp16(b_base + (uint32_t)(lrow * SAH + ch * 8) * 2,
                 W + (size_t)(n0 + lrow) * EMB + k0 + ch * 8);
        }
    };

    load_stage(0, 0);
    cp_commit();

    #pragma unroll 1
    for (int c = 0; c < NKIT; c++) {
        const int cur = c & 1;
        if (c + 1 < NKIT) {
            load_stage((c + 1) * BKH, cur ^ 1);
            cp_commit();
            cp_wait<1>();
        } else {
            cp_wait<0>();
        }
        __syncthreads();

        const __half* Ah = smh + (size_t)cur * TILE_HALVES;
        const __half* Bh = smh + (size_t)(2 + cur) * TILE_HALVES;

        #pragma unroll
        for (int ks = 0; ks < 4; ks++) {
            uint32_t af[4][4], bf[4][2];
            #pragma unroll
            for (int mt = 0; mt < 4; mt++) {
                const int r = wm * 64 + mt * 16 + g;
                const __half* ap = Ah + r * SAH + ks * 16 + tg * 2;
                af[mt][0] = *(const uint32_t*)(ap);
                af[mt][1] = *(const uint32_t*)(ap + 8 * SAH);
                af[mt][2] = *(const uint32_t*)(ap + 8);
                af[mt][3] = *(const uint32_t*)(ap + 8 * SAH + 8);
            }
            #pragma unroll
            for (int nt = 0; nt < 4; nt++) {
                const int n = wn * 32 + nt * 8 + g;
                const __half* bp = Bh + n * SAH + ks * 16 + tg * 2;
                bf[nt][0] = *(const uint32_t*)(bp);
                bf[nt][1] = *(const uint32_t*)(bp + 8);
            }
            #pragma unroll
            for (int mt = 0; mt < 4; mt++)
                #pragma unroll
                for (int nt = 0; nt < 4; nt++)
                    mma_f16(acc[mt][nt], af[mt], bf[nt]);
        }
        __syncthreads();
    }

    // epilogue: bias add + half2 stores
    #pragma unroll
    for (int mt = 0; mt < 4; mt++) {
        const int r = m0 + wm * 64 + mt * 16 + g;
        #pragma unroll
        for (int nt = 0; nt < 4; nt++) {
            const int cn = n0 + wn * 32 + nt * 8 + tg * 2;
            const float2 bb = *(const float2*)(bias + cn);
            __half2 v0 = __floats2half2_rn(acc[mt][nt][0] + bb.x,
                                           acc[mt][nt][1] + bb.y);
            __half2 v1 = __floats2half2_rn(acc[mt][nt][2] + bb.x,
                                           acc[mt][nt][3] + bb.y);
            *(__half2*)(C + (size_t)r * EMB + cn)       = v0;
            *(__half2*)(C + (size_t)(r + 8) * EMB + cn) = v1;
        }
    }
}

// ---------------- partial sums of x over n (16 partials per batch) ------------
__global__ __launch_bounds__(256)
void xpart_kernel(const float* __restrict__ x, float* __restrict__ xpart) {
    __shared__ float4 stage[128];
    const int b = blockIdx.x;                 // 0..1
    const int c = blockIdx.y;                 // 0..15 (128-row chunk)
    const int t = threadIdx.x;
    const int fc = t & 127;                   // float4 column
    const int half = t >> 7;                  // 0/1

    const float4* base = (const float4*)(x + ((size_t)b * N_SEQ + c * 128 + half * 64) * EMB);
    float4 s = make_float4(0.f, 0.f, 0.f, 0.f);
    #pragma unroll 8
    for (int n = 0; n < 64; n++) {
        float4 v = base[(size_t)n * (EMB / 4) + fc];
        s.x += v.x; s.y += v.y; s.z += v.z; s.w += v.w;
    }
    if (half == 1) stage[fc] = s;
    __syncthreads();
    if (half == 0) {
        float4 o = stage[fc];
        o.x += s.x; o.y += s.y; o.z += s.z; o.w += s.w;
        *(float4*)(xpart + ((size_t)b * 16 + c) * EMB + fc * 4) = o;
    }
}

// ---------------- basis: bs[b][j][row] = dot(Wv[row], vec_j) + bv*scale --------
// grid (2, 64): warp w handles row = blockIdx.y*8 + w; 4 dots per warp.
__global__ __launch_bounds__(256)
void basis_kernel(const float* __restrict__ x, const float* __restrict__ xpart,
                  const float* __restrict__ Wv, const float* __restrict__ bv,
                  float* __restrict__ bs) {
    __shared__ float vec[4 * EMB];
    const int b = blockIdx.x;
    const int t = threadIdx.x;
    const int w = t >> 5, lane = t & 31;

    // vec0 = xsum (reduce 16 partials); vec1..3 = x rows 0..2
    if (t < 128) {
        const float4* xp = (const float4*)(xpart + (size_t)b * 16 * EMB) + t;
        float4 s = make_float4(0.f, 0.f, 0.f, 0.f);
        #pragma unroll
        for (int r = 0; r < 16; r++) {
            float4 v = xp[(size_t)r * (EMB / 4)];
            s.x += v.x; s.y += v.y; s.z += v.z; s.w += v.w;
        }
        *(float4*)(vec + t * 4) = s;
    } else {
        const int fc = t - 128;             // 0..127
        #pragma unroll
        for (int j = 1; j < 4; j++) {
            float4 v = *(const float4*)(x + ((size_t)b * N_SEQ + (j - 1)) * EMB + fc * 4);
            *(float4*)(vec + j * EMB + fc * 4) = v;
        }
    }
    __syncthreads();

    const int row = blockIdx.y * 8 + w;     // 0..511
    const float4* wr = (const float4*)(Wv + (size_t)row * EMB);
    float4 wv[4];
    #pragma unroll
    for (int i = 0; i < 4; i++) wv[i] = wr[lane + 32 * i];

    float a[4];
    #pragma unroll
    for (int j = 0; j < 4; j++) {
        const float4* vr = (const float4*)(vec + j * EMB);
        float s = 0.f;
        #pragma unroll
        for (int i = 0; i < 4; i++) {
            float4 vv = vr[lane + 32 * i];
            s += wv[i].x * vv.x + wv[i].y * vv.y + wv[i].z * vv.z + wv[i].w * vv.w;
        }
        a[j] = s;
    }
    #pragma unroll
    for (int off = 16; off; off >>= 1)
        #pragma unroll
        for (int j = 0; j < 4; j++)
            a[j] += __shfl_xor_sync(0xffffffff, a[j], off);
    if (lane < 4) {
        const int j = lane;
        const float scale = (j == 0) ? (float)N_SEQ : 1.f;
        bs[((size_t)b * 4 + j) * EMB + row] = a[j] + bv[row] * scale;
    }
}

// ---------------- U[b][h][j][eo] = sum_d Wo[eo][h*64+d] * bs[b][j][h*64+d] -----
// grid (16 bh, 4 slices of 128 eo); Wo slice staged in smem.
__global__ __launch_bounds__(256)
void u_kernel(const float* __restrict__ bs, const float* __restrict__ Wo,
              float* __restrict__ U) {
    __shared__ float sWo[128 * 65];
    __shared__ float sbs[4][HD];
    const int bh = blockIdx.x;          // 0..15
    const int b = bh >> 3, h = bh & 7;
    const int eo0 = blockIdx.y * 128;
    const int t = threadIdx.x;

    if (t < 4 * HD) {
        const int j = t >> 6, d = t & 63;
        sbs[j][d] = bs[((size_t)b * 4 + j) * EMB + h * HD + d];
    }
    // stage Wo[eo0:eo0+128][h*64:h*64+64] (2048 float4s, 8 per thread)
    #pragma unroll
    for (int i = 0; i < 8; i++) {
        const int fi = t + 256 * i;
        const int r = fi >> 4, c4 = fi & 15;
        float4 v = *(const float4*)(Wo + (size_t)(eo0 + r) * EMB + h * HD + c4 * 4);
        float* dst = sWo + r * 65 + c4 * 4;
        dst[0] = v.x; dst[1] = v.y; dst[2] = v.z; dst[3] = v.w;
    }
    __syncthreads();

    const int eo = t & 127;
    const int jp = t >> 7;              // 0/1 -> j pair {0,1} or {2,3}
    const float* wrow = sWo + eo * 65;
    float a0 = 0.f, a1 = 0.f;
    #pragma unroll 8
    for (int d = 0; d < HD; d++) {
        const float wv = wrow[d];
        a0 = fmaf(wv, sbs[jp * 2][d],     a0);
        a1 = fmaf(wv, sbs[jp * 2 + 1][d], a1);
    }
    U[((size_t)(b * NHEAD + h) * 4 + jp * 2)     * EMB + eo0 + eo] = a0;
    U[((size_t)(b * NHEAD + h) * 4 + jp * 2 + 1) * EMB + eo0 + eo] = a1;
}

// ---------------- fused coef + out ----------------------------------------------
__global__ __launch_bounds__(256)
void coef_out_kernel(const __half* __restrict__ Q, const __half* __restrict__ K,
                     const float* __restrict__ U, const float* __restrict__ bo,
                     float* __restrict__ out) {
    const int blk = blockIdx.x;                 // 0..255
    const int b = blk >> 7;
    const int r0 = (blk & 127) * 16;
    const int t = threadIdx.x;
    const int h = t >> 5;                       // warp = head
    const int lane = t & 31;

    // phase 0: U columns for this thread (coalesced)
    float u0[32], u1[32];
    #pragma unroll
    for (int hj = 0; hj < 32; hj++) {
        u0[hj] = U[((size_t)b * 32 + hj) * EMB + t];
        u1[hj] = U[((size_t)b * 32 + hj) * EMB + t + 256];
    }

    // phase 1: coefficients (warp h; lane covers 2 head-dims via half2)
    __shared__ float sc[16][32];
    const size_t base = ((size_t)b * N_SEQ) * EMB + h * HD;
    #pragma unroll 2
    for (int rr = 0; rr < 16; rr++) {
        const int r = r0 + rr;
        const __half2 q2 = ((const __half2*)(Q + base + (size_t)r * EMB))[lane];
        const float2 qf = __half22float2(q2);
        float v[3];
        bool valid[3];
        #pragma unroll
        for (int c = 0; c < 3; c++) {
            const int kr = r + c - 1;
            valid[c] = (kr >= 0 && kr < N_SEQ);
            if (valid[c]) {
                const __half2 k2 = ((const __half2*)(K + base + (size_t)kr * EMB))[lane];
                const float2 kf = __half22float2(k2);
                v[c] = qf.x * kf.x + qf.y * kf.y;
            } else v[c] = 0.f;
        }
        #pragma unroll
        for (int off = 16; off; off >>= 1)
            #pragma unroll
            for (int c = 0; c < 3; c++)
                v[c] += __shfl_xor_sync(0xffffffff, v[c], off);
        float e[3];
        #pragma unroll
        for (int c = 0; c < 3; c++)
            e[c] = valid[c] ? (expf(v[c]) - 1.f) : 0.f;
        const float inv = 1.f / ((float)N_SEQ + e[0] + e[1] + e[2]);
        if (lane < 4)
            sc[rr][h * 4 + lane] = (lane == 0) ? inv : inv * e[lane - 1];
    }
    __syncthreads();

    // phase 2: combine
    const float bo0 = bo[t], bo1 = bo[t + 256];
    #pragma unroll 2
    for (int rr = 0; rr < 16; rr++) {
        float a0 = bo0, a1 = bo1;
        #pragma unroll
        for (int hj = 0; hj < 32; hj++) {
            const float c = sc[rr][hj];
            a0 = fmaf(c, u0[hj], a0);
            a1 = fmaf(c, u1[hj], a1);
        }
        const size_t ob = ((size_t)b * N_SEQ + r0 + rr) * EMB;
        out[ob + t]       = a0;
        out[ob + t + 256] = a1;
    }
}

// ---------------- launch ----------------------------------------------------------
extern "C" void kernel_launch(void* const* d_in, const int* in_sizes, int n_in,
                              void* d_out, int out_size) {
    const float* x  = (const float*)d_in[0];
    const float* Wq = (const float*)d_in[1];
    const float* bq = (const float*)d_in[2];
    const float* Wk = (const float*)d_in[3];
    const float* bk = (const float*)d_in[4];
    const float* Wv = (const float*)d_in[5];
    const float* bv = (const float*)d_in[6];
    const float* Wo = (const float*)d_in[7];
    const float* bo = (const float*)d_in[8];
    float* outp = (float*)d_out;

    __half *xh, *wqh, *wkh, *Qp, *Kp;
    float *xpp, *bsp, *Up;
    cudaGetSymbolAddress((void**)&xh,  g_xh);
    cudaGetSymbolAddress((void**)&wqh, g_wqh);
    cudaGetSymbolAddress((void**)&wkh, g_wkh);
    cudaGetSymbolAddress((void**)&Qp,  g_Qh);
    cudaGetSymbolAddress((void**)&Kp,  g_Kh);
    cudaGetSymbolAddress((void**)&xpp, g_xpart);
    cudaGetSymbolAddress((void**)&bsp, g_bs);
    cudaGetSymbolAddress((void**)&Up,  g_U);

    cudaFuncSetAttribute(qk_gemm_f16,
                         cudaFuncAttributeMaxDynamicSharedMemorySize, GEMM_SMEM);

    prep_half<<<640, 256>>>(x, Wq, Wk, xh, wqh, wkh);

    qk_gemm_f16<<<dim3(M_ROWS / 128, EMB / 128, 2), 256, GEMM_SMEM>>>(
        xh, wqh, bq, wkh, bk, Qp, Kp);

    xpart_kernel<<<dim3(BATCH, 16), 256>>>(x, xpp);
    basis_kernel<<<dim3(BATCH, 64), 256>>>(x, xpp, Wv, bv, bsp);
    u_kernel<<<dim3(BATCH * NHEAD, 4), 256>>>(bsp, Wo, Up);

    coef_out_kernel<<<256, 256>>>(Qp, Kp, Up, bo, outp);
}

// round 12
// speedup vs baseline: 6.0751x; 1.0470x over previous
#include <cuda_runtime.h>
#include <cuda_fp16.h>
#include <math.h>
#include <stdint.h>

// Problem constants
#define BATCH   2
#define N_SEQ   2048
#define EMB     512
#define NHEAD   8
#define HD      64
#define M_ROWS  (BATCH * N_SEQ)   // 4096

// ---------------- scratch ----------------------------------------------------
__device__ __half g_xh[M_ROWS * EMB];
__device__ __half g_wqh[EMB * EMB];
__device__ __half g_wkh[EMB * EMB];
__device__ __half g_Qh[M_ROWS * EMB];
__device__ __half g_Kh[M_ROWS * EMB];
__device__ float  g_xpart[BATCH * 16 * EMB];
__device__ float  g_vec[BATCH * 4 * EMB];         // [b][j][512]: vsum, x0, x1, x2
__device__ float  g_bs[BATCH * 4 * EMB];          // [b][j][row(=h*64+d)]
__device__ float  g_U[BATCH * NHEAD * 4 * EMB];

// ---------------- helpers ------------------------------------------------------
__device__ __forceinline__ uint32_t smem_u32(const void* p) {
    uint32_t a;
    asm("{ .reg .u64 t; cvta.to.shared.u64 t, %1; cvt.u32.u64 %0, t; }"
        : "=r"(a) : "l"(p));
    return a;
}

__device__ __forceinline__ void cp16(uint32_t dst, const void* src) {
    asm volatile("cp.async.cg.shared.global [%0], [%1], 16;"
                 :: "r"(dst), "l"(src) : "memory");
}
__device__ __forceinline__ void cp_commit() {
    asm volatile("cp.async.commit_group;" ::: "memory");
}
template <int N> __device__ __forceinline__ void cp_wait() {
    asm volatile("cp.async.wait_group %0;" :: "n"(N) : "memory");
}

__device__ __forceinline__ void mma_f16(float d[4], const uint32_t a[4],
                                        const uint32_t b[2]) {
    asm volatile(
        "mma.sync.aligned.m16n8k16.row.col.f32.f16.f16.f32 "
        "{%0,%1,%2,%3}, {%4,%5,%6,%7}, {%8,%9}, {%0,%1,%2,%3};"
        : "+f"(d[0]), "+f"(d[1]), "+f"(d[2]), "+f"(d[3])
        : "r"(a[0]), "r"(a[1]), "r"(a[2]), "r"(a[3]), "r"(b[0]), "r"(b[1]));
}

// ---------------- fp32 -> fp16 pre-convert ------------------------------------
#define PH_X_F4 (M_ROWS * EMB / 4)   // 524288
#define PH_W_F4 (EMB * EMB / 4)      // 65536

__global__ __launch_bounds__(256)
void prep_half(const float* __restrict__ x, const float* __restrict__ Wq,
               const float* __restrict__ Wk, __half* __restrict__ xh,
               __half* __restrict__ wqh, __half* __restrict__ wkh) {
    const int total = PH_X_F4 + 2 * PH_W_F4;
    for (int i = blockIdx.x * blockDim.x + threadIdx.x; i < total;
         i += gridDim.x * blockDim.x) {
        const float4* src;
        __half2* dst;
        int off;
        if (i < PH_X_F4)                { src = (const float4*)x;  dst = (__half2*)xh;  off = i; }
        else if (i < PH_X_F4 + PH_W_F4) { src = (const float4*)Wq; dst = (__half2*)wqh; off = i - PH_X_F4; }
        else                            { src = (const float4*)Wk; dst = (__half2*)wkh; off = i - PH_X_F4 - PH_W_F4; }
        float4 v = src[off];
        dst[off * 2]     = __floats2half2_rn(v.x, v.y);
        dst[off * 2 + 1] = __floats2half2_rn(v.z, v.w);
    }
}

// ---------------- fp16 mma.sync GEMM: Q,K = X @ W.T + b (fp16 out) -------------
// CTA tile 128x256, 16 warps (2x8), warp tile 64x32, 3-stage cp.async pipeline.
#define GBM 128
#define GBN 256
#define BKH 64
#define SAH 72                          // padded row stride in halves
#define A_TILE_H (GBM * SAH)            // 9216 halves
#define B_TILE_H (GBN * SAH)            // 18432 halves
#define A_BYTES  (A_TILE_H * 2)         // 18432
#define STAGE_BYTES ((A_TILE_H + B_TILE_H) * 2)   // 55296
#define NSTAGE 3
#define NKIT (EMB / BKH)                // 8
#define GEMM_SMEM (STAGE_BYTES * NSTAGE)          // 165888

__global__ __launch_bounds__(512, 1)
void qk_gemm_f16(const __half* __restrict__ xh,
                 const __half* __restrict__ wqh, const float* __restrict__ bq,
                 const __half* __restrict__ wkh, const float* __restrict__ bk,
                 __half* __restrict__ Qout, __half* __restrict__ Kout) {
    extern __shared__ __half smh[];
    const int tid  = threadIdx.x;
    const int wid  = tid >> 5;
    const int lane = tid & 31;
    const int wm   = wid >> 3;          // 0..1
    const int wn   = wid & 7;           // 0..7
    const int g    = lane >> 2;         // 0..7
    const int tg   = lane & 3;          // 0..3

    const __half* W    = blockIdx.z ? wkh : wqh;
    const float*  bias = blockIdx.z ? bk  : bq;
    __half*       C    = blockIdx.z ? Kout : Qout;
    const int m0 = blockIdx.x * GBM;
    const int n0 = blockIdx.y * GBN;

    const uint32_t uS = smem_u32(smh);

    float acc[4][4][4];
    #pragma unroll
    for (int i = 0; i < 4; i++)
        #pragma unroll
        for (int j = 0; j < 4; j++)
            #pragma unroll
            for (int k = 0; k < 4; k++) acc[i][j][k] = 0.f;

    const int arow = tid >> 2;          // 0..127
    const int acb  = (tid & 3) * 2;     // A chunk base
    const int brow = tid >> 1;          // 0..255
    const int bcb  = (tid & 1) * 4;     // B chunk base

    auto load_stage = [&](int k0, int s) {
        const uint32_t base = uS + (uint32_t)s * STAGE_BYTES;
        #pragma unroll
        for (int i = 0; i < 2; i++) {
            const int ch = acb + i;
            cp16(base + (uint32_t)(arow * SAH + ch * 8) * 2,
                 xh + (size_t)(m0 + arow) * EMB + k0 + ch * 8);
        }
        #pragma unroll
        for (int i = 0; i < 4; i++) {
            const int ch = bcb + i;
            cp16(base + A_BYTES + (uint32_t)(brow * SAH + ch * 8) * 2,
                 W + (size_t)(n0 + brow) * EMB + k0 + ch * 8);
        }
    };

    load_stage(0, 0);
    cp_commit();
    load_stage(BKH, 1);
    cp_commit();

    #pragma unroll 1
    for (int c = 0; c < NKIT; c++) {
        if (c <= NKIT - 2) { cp_wait<1>(); } else { cp_wait<0>(); }
        __syncthreads();
        if (c + 2 < NKIT) {
            load_stage((c + 2) * BKH, (c + 2) % NSTAGE);
            cp_commit();
        }

        const __half* Ah = smh + (size_t)(c % NSTAGE) * (STAGE_BYTES / 2);
        const __half* Bh = Ah + A_TILE_H;

        #pragma unroll
        for (int ks = 0; ks < 4; ks++) {
            uint32_t af[4][4], bf[4][2];
            #pragma unroll
            for (int mt = 0; mt < 4; mt++) {
                const int r = wm * 64 + mt * 16 + g;
                const __half* ap = Ah + r * SAH + ks * 16 + tg * 2;
                af[mt][0] = *(const uint32_t*)(ap);
                af[mt][1] = *(const uint32_t*)(ap + 8 * SAH);
                af[mt][2] = *(const uint32_t*)(ap + 8);
                af[mt][3] = *(const uint32_t*)(ap + 8 * SAH + 8);
            }
            #pragma unroll
            for (int nt = 0; nt < 4; nt++) {
                const int n = wn * 32 + nt * 8 + g;
                const __half* bp = Bh + n * SAH + ks * 16 + tg * 2;
                bf[nt][0] = *(const uint32_t*)(bp);
                bf[nt][1] = *(const uint32_t*)(bp + 8);
            }
            #pragma unroll
            for (int mt = 0; mt < 4; mt++)
                #pragma unroll
                for (int nt = 0; nt < 4; nt++)
                    mma_f16(acc[mt][nt], af[mt], bf[nt]);
        }
    }

    // epilogue: bias add + half2 stores
    #pragma unroll
    for (int mt = 0; mt < 4; mt++) {
        const int r = m0 + wm * 64 + mt * 16 + g;
        #pragma unroll
        for (int nt = 0; nt < 4; nt++) {
            const int cn = n0 + wn * 32 + nt * 8 + tg * 2;
            const float2 bb = *(const float2*)(bias + cn);
            __half2 v0 = __floats2half2_rn(acc[mt][nt][0] + bb.x,
                                           acc[mt][nt][1] + bb.y);
            __half2 v1 = __floats2half2_rn(acc[mt][nt][2] + bb.x,
                                           acc[mt][nt][3] + bb.y);
            *(__half2*)(C + (size_t)r * EMB + cn)       = v0;
            *(__half2*)(C + (size_t)(r + 8) * EMB + cn) = v1;
        }
    }
}

// ---------------- partial sums of x over n (16 partials per batch) ------------
__global__ __launch_bounds__(256)
void xpart_kernel(const float* __restrict__ x, float* __restrict__ xpart) {
    __shared__ float4 stage[128];
    const int b = blockIdx.x;                 // 0..1
    const int c = blockIdx.y;                 // 0..15 (128-row chunk)
    const int t = threadIdx.x;
    const int fc = t & 127;                   // float4 column
    const int half = t >> 7;                  // 0/1

    const float4* base = (const float4*)(x + ((size_t)b * N_SEQ + c * 128 + half * 64) * EMB);
    float4 s = make_float4(0.f, 0.f, 0.f, 0.f);
    #pragma unroll 8
    for (int n = 0; n < 64; n++) {
        float4 v = base[(size_t)n * (EMB / 4) + fc];
        s.x += v.x; s.y += v.y; s.z += v.z; s.w += v.w;
    }
    if (half == 1) stage[fc] = s;
    __syncthreads();
    if (half == 0) {
        float4 o = stage[fc];
        o.x += s.x; o.y += s.y; o.z += s.z; o.w += s.w;
        *(float4*)(xpart + ((size_t)b * 16 + c) * EMB + fc * 4) = o;
    }
}

// ---------------- vec finalize: vsum + x rows 0..2 into one gmem buffer -------
__global__ __launch_bounds__(256)
void vec_kernel(const float* __restrict__ x, const float* __restrict__ xpart,
                float* __restrict__ vec) {
    const int b = blockIdx.x;
    const int t = threadIdx.x;                // handles float2 column t
    const float2* xp = (const float2*)(xpart + (size_t)b * 16 * EMB) + t;
    float2 s = make_float2(0.f, 0.f);
    #pragma unroll
    for (int r = 0; r < 16; r++) {
        float2 v = xp[(size_t)r * (EMB / 2)];
        s.x += v.x; s.y += v.y;
    }
    ((float2*)(vec + (size_t)b * 4 * EMB))[t] = s;
    #pragma unroll
    for (int j = 1; j < 4; j++) {
        float2 v = ((const float2*)(x + ((size_t)b * N_SEQ + (j - 1)) * EMB))[t];
        ((float2*)(vec + ((size_t)b * 4 + j) * EMB))[t] = v;
    }
}

// ---------------- basis: bs[b][j][row] = dot(Wv[row], vec_j) + bv*scale --------
// grid (2, 64): warp w handles row = blockIdx.y*8 + w; vec read from L2-hot gmem.
__global__ __launch_bounds__(256)
void basis_kernel(const float* __restrict__ vec, const float* __restrict__ Wv,
                  const float* __restrict__ bv, float* __restrict__ bs) {
    const int b = blockIdx.x;
    const int t = threadIdx.x;
    const int w = t >> 5, lane = t & 31;

    const int row = blockIdx.y * 8 + w;     // 0..511
    const float4* wr = (const float4*)(Wv + (size_t)row * EMB);
    float4 wv[4];
    #pragma unroll
    for (int i = 0; i < 4; i++) wv[i] = wr[lane + 32 * i];

    float a[4];
    #pragma unroll
    for (int j = 0; j < 4; j++) {
        const float4* vr = (const float4*)(vec + ((size_t)b * 4 + j) * EMB);
        float s = 0.f;
        #pragma unroll
        for (int i = 0; i < 4; i++) {
            float4 vv = vr[lane + 32 * i];
            s += wv[i].x * vv.x + wv[i].y * vv.y + wv[i].z * vv.z + wv[i].w * vv.w;
        }
        a[j] = s;
    }
    #pragma unroll
    for (int off = 16; off; off >>= 1)
        #pragma unroll
        for (int j = 0; j < 4; j++)
            a[j] += __shfl_xor_sync(0xffffffff, a[j], off);
    if (lane < 4) {
        const int j = lane;
        const float scale = (j == 0) ? (float)N_SEQ : 1.f;
        bs[((size_t)b * 4 + j) * EMB + row] = a[j] + bv[row] * scale;
    }
}

// ---------------- U[b][h][j][eo] = sum_d Wo[eo][h*64+d] * bs[b][j][h*64+d] -----
__global__ __launch_bounds__(256)
void u_kernel(const float* __restrict__ bs, const float* __restrict__ Wo,
              float* __restrict__ U) {
    __shared__ float sWo[128 * 65];
    __shared__ float sbs[4][HD];
    const int bh = blockIdx.x;          // 0..15
    const int b = bh >> 3, h = bh & 7;
    const int eo0 = blockIdx.y * 128;
    const int t = threadIdx.x;

    if (t < 4 * HD) {
        const int j = t >> 6, d = t & 63;
        sbs[j][d] = bs[((size_t)b * 4 + j) * EMB + h * HD + d];
    }
    #pragma unroll
    for (int i = 0; i < 8; i++) {
        const int fi = t + 256 * i;
        const int r = fi >> 4, c4 = fi & 15;
        float4 v = *(const float4*)(Wo + (size_t)(eo0 + r) * EMB + h * HD + c4 * 4);
        float* dst = sWo + r * 65 + c4 * 4;
        dst[0] = v.x; dst[1] = v.y; dst[2] = v.z; dst[3] = v.w;
    }
    __syncthreads();

    const int eo = t & 127;
    const int jp = t >> 7;              // 0/1 -> j pair {0,1} or {2,3}
    const float* wrow = sWo + eo * 65;
    float a0 = 0.f, a1 = 0.f;
    #pragma unroll 8
    for (int d = 0; d < HD; d++) {
        const float wv = wrow[d];
        a0 = fmaf(wv, sbs[jp * 2][d],     a0);
        a1 = fmaf(wv, sbs[jp * 2 + 1][d], a1);
    }
    U[((size_t)(b * NHEAD + h) * 4 + jp * 2)     * EMB + eo0 + eo] = a0;
    U[((size_t)(b * NHEAD + h) * 4 + jp * 2 + 1) * EMB + eo0 + eo] = a1;
}

// ---------------- fused coef + out ----------------------------------------------
__global__ __launch_bounds__(256)
void coef_out_kernel(const __half* __restrict__ Q, const __half* __restrict__ K,
                     const float* __restrict__ U, const float* __restrict__ bo,
                     float* __restrict__ out) {
    const int blk = blockIdx.x;                 // 0..255
    const int b = blk >> 7;
    const int r0 = (blk & 127) * 16;
    const int t = threadIdx.x;
    const int h = t >> 5;                       // warp = head
    const int lane = t & 31;

    // phase 0: U columns for this thread (coalesced)
    float u0[32], u1[32];
    #pragma unroll
    for (int hj = 0; hj < 32; hj++) {
        u0[hj] = U[((size_t)b * 32 + hj) * EMB + t];
        u1[hj] = U[((size_t)b * 32 + hj) * EMB + t + 256];
    }

    // phase 1: coefficients (warp h; lane covers 2 head-dims via half2)
    __shared__ float sc[16][32];
    const size_t base = ((size_t)b * N_SEQ) * EMB + h * HD;
    #pragma unroll 2
    for (int rr = 0; rr < 16; rr++) {
        const int r = r0 + rr;
        const __half2 q2 = ((const __half2*)(Q + base + (size_t)r * EMB))[lane];
        const float2 qf = __half22float2(q2);
        float v[3];
        bool valid[3];
        #pragma unroll
        for (int c = 0; c < 3; c++) {
            const int kr = r + c - 1;
            valid[c] = (kr >= 0 && kr < N_SEQ);
            if (valid[c]) {
                const __half2 k2 = ((const __half2*)(K + base + (size_t)kr * EMB))[lane];
                const float2 kf = __half22float2(k2);
                v[c] = qf.x * kf.x + qf.y * kf.y;
            } else v[c] = 0.f;
        }
        #pragma unroll
        for (int off = 16; off; off >>= 1)
            #pragma unroll
            for (int c = 0; c < 3; c++)
                v[c] += __shfl_xor_sync(0xffffffff, v[c], off);
        float e[3];
        #pragma unroll
        for (int c = 0; c < 3; c++)
            e[c] = valid[c] ? (expf(v[c]) - 1.f) : 0.f;
        const float inv = 1.f / ((float)N_SEQ + e[0] + e[1] + e[2]);
        if (lane < 4)
            sc[rr][h * 4 + lane] = (lane == 0) ? inv : inv * e[lane - 1];
    }
    __syncthreads();

    // phase 2: combine
    const float bo0 = bo[t], bo1 = bo[t + 256];
    #pragma unroll 2
    for (int rr = 0; rr < 16; rr++) {
        float a0 = bo0, a1 = bo1;
        #pragma unroll
        for (int hj = 0; hj < 32; hj++) {
            const float c = sc[rr][hj];
            a0 = fmaf(c, u0[hj], a0);
            a1 = fmaf(c, u1[hj], a1);
        }
        const size_t ob = ((size_t)b * N_SEQ + r0 + rr) * EMB;
        out[ob + t]       = a0;
        out[ob + t + 256] = a1;
    }
}

// ---------------- launch ----------------------------------------------------------
extern "C" void kernel_launch(void* const* d_in, const int* in_sizes, int n_in,
                              void* d_out, int out_size) {
    const float* x  = (const float*)d_in[0];
    const float* Wq = (const float*)d_in[1];
    const float* bq = (const float*)d_in[2];
    const float* Wk = (const float*)d_in[3];
    const float* bk = (const float*)d_in[4];
    const float* Wv = (const float*)d_in[5];
    const float* bv = (const float*)d_in[6];
    const float* Wo = (const float*)d_in[7];
    const float* bo = (const float*)d_in[8];
    float* outp = (float*)d_out;

    __half *xh, *wqh, *wkh, *Qp, *Kp;
    float *xpp, *vcp, *bsp, *Up;
    cudaGetSymbolAddress((void**)&xh,  g_xh);
    cudaGetSymbolAddress((void**)&wqh, g_wqh);
    cudaGetSymbolAddress((void**)&wkh, g_wkh);
    cudaGetSymbolAddress((void**)&Qp,  g_Qh);
    cudaGetSymbolAddress((void**)&Kp,  g_Kh);
    cudaGetSymbolAddress((void**)&xpp, g_xpart);
    cudaGetSymbolAddress((void**)&vcp, g_vec);
    cudaGetSymbolAddress((void**)&bsp, g_bs);
    cudaGetSymbolAddress((void**)&Up,  g_U);

    cudaFuncSetAttribute(qk_gemm_f16,
                         cudaFuncAttributeMaxDynamicSharedMemorySize, GEMM_SMEM);

    prep_half<<<640, 256>>>(x, Wq, Wk, xh, wqh, wkh);

    qk_gemm_f16<<<dim3(M_ROWS / GBM, EMB / GBN, 2), 512, GEMM_SMEM>>>(
        xh, wqh, bq, wkh, bk, Qp, Kp);

    xpart_kernel<<<dim3(BATCH, 16), 256>>>(x, xpp);
    vec_kernel<<<BATCH, 256>>>(x, xpp, vcp);
    basis_kernel<<<dim3(BATCH, 64), 256>>>(vcp, Wv, bv, bsp);
    u_kernel<<<dim3(BATCH * NHEAD, 4), 256>>>(bsp, Wo, Up);

    coef_out_kernel<<<256, 256>>>(Qp, Kp, Up, bo, outp);
}

// round 13
// speedup vs baseline: 6.9248x; 1.1399x over previous
#include <cuda_runtime.h>
#include <cuda_fp16.h>
#include <math.h>
#include <stdint.h>

// Problem constants
#define BATCH   2
#define N_SEQ   2048
#define EMB     512
#define NHEAD   8
#define HD      64
#define M_ROWS  (BATCH * N_SEQ)   // 4096

// ---------------- scratch ----------------------------------------------------
__device__ __half g_xh[M_ROWS * EMB];
__device__ __half g_wqh[EMB * EMB];
__device__ __half g_wkh[EMB * EMB];
__device__ __half g_Qh[M_ROWS * EMB];
__device__ __half g_Kh[M_ROWS * EMB];
__device__ float  g_xpart[BATCH * 16 * EMB];
__device__ float  g_bs[BATCH * 4 * EMB];          // [b][j][row(=h*64+d)]
__device__ float  g_U[BATCH * NHEAD * 4 * EMB];

// ---------------- side stream for the value/output prep branch ----------------
struct SideStream {
    cudaStream_t s2;
    cudaEvent_t  evF, evJ;
    SideStream() {
        cudaStreamCreateWithFlags(&s2, cudaStreamNonBlocking);
        cudaEventCreateWithFlags(&evF, cudaEventDisableTiming);
        cudaEventCreateWithFlags(&evJ, cudaEventDisableTiming);
    }
};
static SideStream g_ss;

// ---------------- helpers ------------------------------------------------------
__device__ __forceinline__ uint32_t smem_u32(const void* p) {
    uint32_t a;
    asm("{ .reg .u64 t; cvta.to.shared.u64 t, %1; cvt.u32.u64 %0, t; }"
        : "=r"(a) : "l"(p));
    return a;
}

__device__ __forceinline__ void cp16(uint32_t dst, const void* src) {
    asm volatile("cp.async.cg.shared.global [%0], [%1], 16;"
                 :: "r"(dst), "l"(src) : "memory");
}
__device__ __forceinline__ void cp_commit() {
    asm volatile("cp.async.commit_group;" ::: "memory");
}
template <int N> __device__ __forceinline__ void cp_wait() {
    asm volatile("cp.async.wait_group %0;" :: "n"(N) : "memory");
}

__device__ __forceinline__ void mma_f16(float d[4], const uint32_t a[4],
                                        const uint32_t b[2]) {
    asm volatile(
        "mma.sync.aligned.m16n8k16.row.col.f32.f16.f16.f32 "
        "{%0,%1,%2,%3}, {%4,%5,%6,%7}, {%8,%9}, {%0,%1,%2,%3};"
        : "+f"(d[0]), "+f"(d[1]), "+f"(d[2]), "+f"(d[3])
        : "r"(a[0]), "r"(a[1]), "r"(a[2]), "r"(a[3]), "r"(b[0]), "r"(b[1]));
}

// ---------------- fp32 -> fp16 pre-convert ------------------------------------
#define PH_X_F4 (M_ROWS * EMB / 4)   // 524288
#define PH_W_F4 (EMB * EMB / 4)      // 65536

__global__ __launch_bounds__(256)
void prep_half(const float* __restrict__ x, const float* __restrict__ Wq,
               const float* __restrict__ Wk, __half* __restrict__ xh,
               __half* __restrict__ wqh, __half* __restrict__ wkh) {
    const int total = PH_X_F4 + 2 * PH_W_F4;
    for (int i = blockIdx.x * blockDim.x + threadIdx.x; i < total;
         i += gridDim.x * blockDim.x) {
        const float4* src;
        __half2* dst;
        int off;
        if (i < PH_X_F4)                { src = (const float4*)x;  dst = (__half2*)xh;  off = i; }
        else if (i < PH_X_F4 + PH_W_F4) { src = (const float4*)Wq; dst = (__half2*)wqh; off = i - PH_X_F4; }
        else                            { src = (const float4*)Wk; dst = (__half2*)wkh; off = i - PH_X_F4 - PH_W_F4; }
        float4 v = src[off];
        dst[off * 2]     = __floats2half2_rn(v.x, v.y);
        dst[off * 2 + 1] = __floats2half2_rn(v.z, v.w);
    }
}

// ---------------- fp16 mma.sync GEMM: Q,K = X @ W.T + b (fp16 out) -------------
// CTA tile 128x256, 16 warps (2x8), warp tile 64x32, 3-stage cp.async pipeline.
#define GBM 128
#define GBN 256
#define BKH 64
#define SAH 72                          // padded row stride in halves
#define A_TILE_H (GBM * SAH)            // 9216 halves
#define B_TILE_H (GBN * SAH)            // 18432 halves
#define A_BYTES  (A_TILE_H * 2)         // 18432
#define STAGE_BYTES ((A_TILE_H + B_TILE_H) * 2)   // 55296
#define NSTAGE 3
#define NKIT (EMB / BKH)                // 8
#define GEMM_SMEM (STAGE_BYTES * NSTAGE)          // 165888

__global__ __launch_bounds__(512, 1)
void qk_gemm_f16(const __half* __restrict__ xh,
                 const __half* __restrict__ wqh, const float* __restrict__ bq,
                 const __half* __restrict__ wkh, const float* __restrict__ bk,
                 __half* __restrict__ Qout, __half* __restrict__ Kout) {
    extern __shared__ __half smh[];
    const int tid  = threadIdx.x;
    const int wid  = tid >> 5;
    const int lane = tid & 31;
    const int wm   = wid >> 3;          // 0..1
    const int wn   = wid & 7;           // 0..7
    const int g    = lane >> 2;         // 0..7
    const int tg   = lane & 3;          // 0..3

    const __half* W    = blockIdx.z ? wkh : wqh;
    const float*  bias = blockIdx.z ? bk  : bq;
    __half*       C    = blockIdx.z ? Kout : Qout;
    const int m0 = blockIdx.x * GBM;
    const int n0 = blockIdx.y * GBN;

    const uint32_t uS = smem_u32(smh);

    float acc[4][4][4];
    #pragma unroll
    for (int i = 0; i < 4; i++)
        #pragma unroll
        for (int j = 0; j < 4; j++)
            #pragma unroll
            for (int k = 0; k < 4; k++) acc[i][j][k] = 0.f;

    const int arow = tid >> 2;          // 0..127
    const int acb  = (tid & 3) * 2;     // A chunk base
    const int brow = tid >> 1;          // 0..255
    const int bcb  = (tid & 1) * 4;     // B chunk base

    auto load_stage = [&](int k0, int s) {
        const uint32_t base = uS + (uint32_t)s * STAGE_BYTES;
        #pragma unroll
        for (int i = 0; i < 2; i++) {
            const int ch = acb + i;
            cp16(base + (uint32_t)(arow * SAH + ch * 8) * 2,
                 xh + (size_t)(m0 + arow) * EMB + k0 + ch * 8);
        }
        #pragma unroll
        for (int i = 0; i < 4; i++) {
            const int ch = bcb + i;
            cp16(base + A_BYTES + (uint32_t)(brow * SAH + ch * 8) * 2,
                 W + (size_t)(n0 + brow) * EMB + k0 + ch * 8);
        }
    };

    load_stage(0, 0);
    cp_commit();
    load_stage(BKH, 1);
    cp_commit();

    #pragma unroll 1
    for (int c = 0; c < NKIT; c++) {
        if (c <= NKIT - 2) { cp_wait<1>(); } else { cp_wait<0>(); }
        __syncthreads();
        if (c + 2 < NKIT) {
            load_stage((c + 2) * BKH, (c + 2) % NSTAGE);
            cp_commit();
        }

        const __half* Ah = smh + (size_t)(c % NSTAGE) * (STAGE_BYTES / 2);
        const __half* Bh = Ah + A_TILE_H;

        #pragma unroll
        for (int ks = 0; ks < 4; ks++) {
            uint32_t af[4][4], bf[4][2];
            #pragma unroll
            for (int mt = 0; mt < 4; mt++) {
                const int r = wm * 64 + mt * 16 + g;
                const __half* ap = Ah + r * SAH + ks * 16 + tg * 2;
                af[mt][0] = *(const uint32_t*)(ap);
                af[mt][1] = *(const uint32_t*)(ap + 8 * SAH);
                af[mt][2] = *(const uint32_t*)(ap + 8);
                af[mt][3] = *(const uint32_t*)(ap + 8 * SAH + 8);
            }
            #pragma unroll
            for (int nt = 0; nt < 4; nt++) {
                const int n = wn * 32 + nt * 8 + g;
                const __half* bp = Bh + n * SAH + ks * 16 + tg * 2;
                bf[nt][0] = *(const uint32_t*)(bp);
                bf[nt][1] = *(const uint32_t*)(bp + 8);
            }
            #pragma unroll
            for (int mt = 0; mt < 4; mt++)
                #pragma unroll
                for (int nt = 0; nt < 4; nt++)
                    mma_f16(acc[mt][nt], af[mt], bf[nt]);
        }
    }

    // epilogue: bias add + half2 stores
    #pragma unroll
    for (int mt = 0; mt < 4; mt++) {
        const int r = m0 + wm * 64 + mt * 16 + g;
        #pragma unroll
        for (int nt = 0; nt < 4; nt++) {
            const int cn = n0 + wn * 32 + nt * 8 + tg * 2;
            const float2 bb = *(const float2*)(bias + cn);
            __half2 v0 = __floats2half2_rn(acc[mt][nt][0] + bb.x,
                                           acc[mt][nt][1] + bb.y);
            __half2 v1 = __floats2half2_rn(acc[mt][nt][2] + bb.x,
                                           acc[mt][nt][3] + bb.y);
            *(__half2*)(C + (size_t)r * EMB + cn)       = v0;
            *(__half2*)(C + (size_t)(r + 8) * EMB + cn) = v1;
        }
    }
}

// ---------------- partial sums of x over n (16 partials per batch) ------------
__global__ __launch_bounds__(256)
void xpart_kernel(const float* __restrict__ x, float* __restrict__ xpart) {
    __shared__ float4 stage[128];
    const int b = blockIdx.x;                 // 0..1
    const int c = blockIdx.y;                 // 0..15 (128-row chunk)
    const int t = threadIdx.x;
    const int fc = t & 127;                   // float4 column
    const int half = t >> 7;                  // 0/1

    const float4* base = (const float4*)(x + ((size_t)b * N_SEQ + c * 128 + half * 64) * EMB);
    float4 s = make_float4(0.f, 0.f, 0.f, 0.f);
    #pragma unroll 8
    for (int n = 0; n < 64; n++) {
        float4 v = base[(size_t)n * (EMB / 4) + fc];
        s.x += v.x; s.y += v.y; s.z += v.z; s.w += v.w;
    }
    if (half == 1) stage[fc] = s;
    __syncthreads();
    if (half == 0) {
        float4 o = stage[fc];
        o.x += s.x; o.y += s.y; o.z += s.z; o.w += s.w;
        *(float4*)(xpart + ((size_t)b * 16 + c) * EMB + fc * 4) = o;
    }
}

// ---------------- basis: bs[b][j][row] = dot(Wv[row], vec_j) + bv*scale --------
// grid (2, 64): builds vec (vsum + x rows 0..2) in smem, then warp w does row.
__global__ __launch_bounds__(256)
void basis_kernel(const float* __restrict__ x, const float* __restrict__ xpart,
                  const float* __restrict__ Wv, const float* __restrict__ bv,
                  float* __restrict__ bs) {
    __shared__ float vec[4 * EMB];
    const int b = blockIdx.x;
    const int t = threadIdx.x;
    const int w = t >> 5, lane = t & 31;

    // vec0 = sum of 16 partials (each thread 2 columns, coalesced)
    #pragma unroll
    for (int rep = 0; rep < 2; rep++) {
        const int col = t + rep * 256;
        float s = 0.f;
        #pragma unroll
        for (int r = 0; r < 16; r++)
            s += xpart[((size_t)b * 16 + r) * EMB + col];
        vec[col] = s;
    }
    // vec1..3 = x rows 0..2 (float2 per thread)
    #pragma unroll
    for (int j = 1; j < 4; j++) {
        float2 v = ((const float2*)(x + ((size_t)b * N_SEQ + (j - 1)) * EMB))[t];
        ((float2*)(vec + j * EMB))[t] = v;
    }
    __syncthreads();

    const int row = blockIdx.y * 8 + w;     // 0..511
    const float4* wr = (const float4*)(Wv + (size_t)row * EMB);
    float4 wv[4];
    #pragma unroll
    for (int i = 0; i < 4; i++) wv[i] = wr[lane + 32 * i];

    float a[4];
    #pragma unroll
    for (int j = 0; j < 4; j++) {
        const float4* vr = (const float4*)(vec + j * EMB);
        float s = 0.f;
        #pragma unroll
        for (int i = 0; i < 4; i++) {
            float4 vv = vr[lane + 32 * i];
            s += wv[i].x * vv.x + wv[i].y * vv.y + wv[i].z * vv.z + wv[i].w * vv.w;
        }
        a[j] = s;
    }
    #pragma unroll
    for (int off = 16; off; off >>= 1)
        #pragma unroll
        for (int j = 0; j < 4; j++)
            a[j] += __shfl_xor_sync(0xffffffff, a[j], off);
    if (lane < 4) {
        const int j = lane;
        const float scale = (j == 0) ? (float)N_SEQ : 1.f;
        bs[((size_t)b * 4 + j) * EMB + row] = a[j] + bv[row] * scale;
    }
}

// ---------------- U[b][h][j][eo] = sum_d Wo[eo][h*64+d] * bs[b][j][h*64+d] -----
__global__ __launch_bounds__(256)
void u_kernel(const float* __restrict__ bs, const float* __restrict__ Wo,
              float* __restrict__ U) {
    __shared__ float sWo[128 * 65];
    __shared__ float sbs[4][HD];
    const int bh = blockIdx.x;          // 0..15
    const int b = bh >> 3, h = bh & 7;
    const int eo0 = blockIdx.y * 128;
    const int t = threadIdx.x;

    if (t < 4 * HD) {
        const int j = t >> 6, d = t & 63;
        sbs[j][d] = bs[((size_t)b * 4 + j) * EMB + h * HD + d];
    }
    #pragma unroll
    for (int i = 0; i < 8; i++) {
        const int fi = t + 256 * i;
        const int r = fi >> 4, c4 = fi & 15;
        float4 v = *(const float4*)(Wo + (size_t)(eo0 + r) * EMB + h * HD + c4 * 4);
        float* dst = sWo + r * 65 + c4 * 4;
        dst[0] = v.x; dst[1] = v.y; dst[2] = v.z; dst[3] = v.w;
    }
    __syncthreads();

    const int eo = t & 127;
    const int jp = t >> 7;              // 0/1 -> j pair {0,1} or {2,3}
    const float* wrow = sWo + eo * 65;
    float a0 = 0.f, a1 = 0.f;
    #pragma unroll 8
    for (int d = 0; d < HD; d++) {
        const float wv = wrow[d];
        a0 = fmaf(wv, sbs[jp * 2][d],     a0);
        a1 = fmaf(wv, sbs[jp * 2 + 1][d], a1);
    }
    U[((size_t)(b * NHEAD + h) * 4 + jp * 2)     * EMB + eo0 + eo] = a0;
    U[((size_t)(b * NHEAD + h) * 4 + jp * 2 + 1) * EMB + eo0 + eo] = a1;
}

// ---------------- fused coef + out ----------------------------------------------
__global__ __launch_bounds__(256)
void coef_out_kernel(const __half* __restrict__ Q, const __half* __restrict__ K,
                     const float* __restrict__ U, const float* __restrict__ bo,
                     float* __restrict__ out) {
    const int blk = blockIdx.x;                 // 0..255
    const int b = blk >> 7;
    const int r0 = (blk & 127) * 16;
    const int t = threadIdx.x;
    const int h = t >> 5;                       // warp = head
    const int lane = t & 31;

    // phase 0: U columns for this thread (coalesced)
    float u0[32], u1[32];
    #pragma unroll
    for (int hj = 0; hj < 32; hj++) {
        u0[hj] = U[((size_t)b * 32 + hj) * EMB + t];
        u1[hj] = U[((size_t)b * 32 + hj) * EMB + t + 256];
    }

    // phase 1: coefficients (warp h; lane covers 2 head-dims via half2)
    __shared__ float sc[16][32];
    const size_t base = ((size_t)b * N_SEQ) * EMB + h * HD;
    #pragma unroll 2
    for (int rr = 0; rr < 16; rr++) {
        const int r = r0 + rr;
        const __half2 q2 = ((const __half2*)(Q + base + (size_t)r * EMB))[lane];
        const float2 qf = __half22float2(q2);
        float v[3];
        bool valid[3];
        #pragma unroll
        for (int c = 0; c < 3; c++) {
            const int kr = r + c - 1;
            valid[c] = (kr >= 0 && kr < N_SEQ);
            if (valid[c]) {
                const __half2 k2 = ((const __half2*)(K + base + (size_t)kr * EMB))[lane];
                const float2 kf = __half22float2(k2);
                v[c] = qf.x * kf.x + qf.y * kf.y;
            } else v[c] = 0.f;
        }
        #pragma unroll
        for (int off = 16; off; off >>= 1)
            #pragma unroll
            for (int c = 0; c < 3; c++)
                v[c] += __shfl_xor_sync(0xffffffff, v[c], off);
        float e[3];
        #pragma unroll
        for (int c = 0; c < 3; c++)
            e[c] = valid[c] ? (expf(v[c]) - 1.f) : 0.f;
        const float inv = 1.f / ((float)N_SEQ + e[0] + e[1] + e[2]);
        if (lane < 4)
            sc[rr][h * 4 + lane] = (lane == 0) ? inv : inv * e[lane - 1];
    }
    __syncthreads();

    // phase 2: combine
    const float bo0 = bo[t], bo1 = bo[t + 256];
    #pragma unroll 2
    for (int rr = 0; rr < 16; rr++) {
        float a0 = bo0, a1 = bo1;
        #pragma unroll
        for (int hj = 0; hj < 32; hj++) {
            const float c = sc[rr][hj];
            a0 = fmaf(c, u0[hj], a0);
            a1 = fmaf(c, u1[hj], a1);
        }
        const size_t ob = ((size_t)b * N_SEQ + r0 + rr) * EMB;
        out[ob + t]       = a0;
        out[ob + t + 256] = a1;
    }
}

// ---------------- launch ----------------------------------------------------------
extern "C" void kernel_launch(void* const* d_in, const int* in_sizes, int n_in,
                              void* d_out, int out_size) {
    const float* x  = (const float*)d_in[0];
    const float* Wq = (const float*)d_in[1];
    const float* bq = (const float*)d_in[2];
    const float* Wk = (const float*)d_in[3];
    const float* bk = (const float*)d_in[4];
    const float* Wv = (const float*)d_in[5];
    const float* bv = (const float*)d_in[6];
    const float* Wo = (const float*)d_in[7];
    const float* bo = (const float*)d_in[8];
    float* outp = (float*)d_out;

    __half *xh, *wqh, *wkh, *Qp, *Kp;
    float *xpp, *bsp, *Up;
    cudaGetSymbolAddress((void**)&xh,  g_xh);
    cudaGetSymbolAddress((void**)&wqh, g_wqh);
    cudaGetSymbolAddress((void**)&wkh, g_wkh);
    cudaGetSymbolAddress((void**)&Qp,  g_Qh);
    cudaGetSymbolAddress((void**)&Kp,  g_Kh);
    cudaGetSymbolAddress((void**)&xpp, g_xpart);
    cudaGetSymbolAddress((void**)&bsp, g_bs);
    cudaGetSymbolAddress((void**)&Up,  g_U);

    cudaFuncSetAttribute(qk_gemm_f16,
                         cudaFuncAttributeMaxDynamicSharedMemorySize, GEMM_SMEM);

    // Fork: value/output prep branch runs concurrently with the Q/K GEMM branch.
    cudaEventRecord(g_ss.evF, 0);
    cudaStreamWaitEvent(g_ss.s2, g_ss.evF, 0);

    // Branch A (main stream): fp16 convert + Q/K GEMM
    prep_half<<<640, 256>>>(x, Wq, Wk, xh, wqh, wkh);
    qk_gemm_f16<<<dim3(M_ROWS / GBM, EMB / GBN, 2), 512, GEMM_SMEM>>>(
        xh, wqh, bq, wkh, bk, Qp, Kp);

    // Branch B (side stream): xsum partials -> basis -> U
    xpart_kernel<<<dim3(BATCH, 16), 256, 0, g_ss.s2>>>(x, xpp);
    basis_kernel<<<dim3(BATCH, 64), 256, 0, g_ss.s2>>>(x, xpp, Wv, bv, bsp);
    u_kernel<<<dim3(BATCH * NHEAD, 4), 256, 0, g_ss.s2>>>(bsp, Wo, Up);

    // Join, then final combine
    cudaEventRecord(g_ss.evJ, g_ss.s2);
    cudaStreamWaitEvent(0, g_ss.evJ, 0);

    coef_out_kernel<<<256, 256>>>(Qp, Kp, Up, bo, outp);
}

// round 14
// speedup vs baseline: 7.1251x; 1.0289x over previous
#include <cuda_runtime.h>
#include <cuda_fp16.h>
#include <math.h>
#include <stdint.h>

// Problem constants
#define BATCH   2
#define N_SEQ   2048
#define EMB     512
#define NHEAD   8
#define HD      64
#define M_ROWS  (BATCH * N_SEQ)   // 4096

// ---------------- scratch ----------------------------------------------------
__device__ __half g_xh[M_ROWS * EMB];
__device__ __half g_wqh[EMB * EMB];
__device__ __half g_wkh[EMB * EMB];
__device__ __half g_Qh[M_ROWS * EMB];
__device__ __half g_Kh[M_ROWS * EMB];
__device__ float  g_xpart[BATCH * 16 * EMB];
__device__ float  g_bs[BATCH * 4 * EMB];          // [b][j][row(=h*64+d)]
__device__ float  g_U[BATCH * NHEAD * 4 * EMB];

// ---------------- side stream for the value/output prep branch ----------------
struct SideStream {
    cudaStream_t s2;
    cudaEvent_t  evF, evJ;
    SideStream() {
        cudaStreamCreateWithFlags(&s2, cudaStreamNonBlocking);
        cudaEventCreateWithFlags(&evF, cudaEventDisableTiming);
        cudaEventCreateWithFlags(&evJ, cudaEventDisableTiming);
    }
};
static SideStream g_ss;

// ---------------- helpers ------------------------------------------------------
__device__ __forceinline__ uint32_t smem_u32(const void* p) {
    uint32_t a;
    asm("{ .reg .u64 t; cvta.to.shared.u64 t, %1; cvt.u32.u64 %0, t; }"
        : "=r"(a) : "l"(p));
    return a;
}

__device__ __forceinline__ void cp16(uint32_t dst, const void* src) {
    asm volatile("cp.async.cg.shared.global [%0], [%1], 16;"
                 :: "r"(dst), "l"(src) : "memory");
}
__device__ __forceinline__ void cp_commit() {
    asm volatile("cp.async.commit_group;" ::: "memory");
}
template <int N> __device__ __forceinline__ void cp_wait() {
    asm volatile("cp.async.wait_group %0;" :: "n"(N) : "memory");
}

__device__ __forceinline__ void mma_f16(float d[4], const uint32_t a[4],
                                        const uint32_t b0, const uint32_t b1) {
    asm volatile(
        "mma.sync.aligned.m16n8k16.row.col.f32.f16.f16.f32 "
        "{%0,%1,%2,%3}, {%4,%5,%6,%7}, {%8,%9}, {%0,%1,%2,%3};"
        : "+f"(d[0]), "+f"(d[1]), "+f"(d[2]), "+f"(d[3])
        : "r"(a[0]), "r"(a[1]), "r"(a[2]), "r"(a[3]), "r"(b0), "r"(b1));
}

__device__ __forceinline__ void ldsm_x4(uint32_t& r0, uint32_t& r1,
                                        uint32_t& r2, uint32_t& r3, uint32_t addr) {
    asm volatile("ldmatrix.sync.aligned.m8n8.x4.shared.b16 {%0,%1,%2,%3}, [%4];"
                 : "=r"(r0), "=r"(r1), "=r"(r2), "=r"(r3) : "r"(addr));
}

// ---------------- fused fp32->fp16 convert + x partial sums --------------------
#define PH_X_F4 (M_ROWS * EMB / 4)   // 524288
#define PH_W_F4 (EMB * EMB / 4)      // 65536
#define PREP_BLOCKS 640

__global__ __launch_bounds__(256)
void prep_fused(const float* __restrict__ x, const float* __restrict__ Wq,
                const float* __restrict__ Wk, __half* __restrict__ xh,
                __half* __restrict__ wqh, __half* __restrict__ wkh,
                float* __restrict__ xpart) {
    const int t = threadIdx.x;
    if (blockIdx.x < PREP_BLOCKS) {
        const int total = PH_X_F4 + 2 * PH_W_F4;
        for (int i = blockIdx.x * 256 + t; i < total; i += PREP_BLOCKS * 256) {
            const float4* src;
            __half2* dst;
            int off;
            if (i < PH_X_F4)                { src = (const float4*)x;  dst = (__half2*)xh;  off = i; }
            else if (i < PH_X_F4 + PH_W_F4) { src = (const float4*)Wq; dst = (__half2*)wqh; off = i - PH_X_F4; }
            else                            { src = (const float4*)Wk; dst = (__half2*)wkh; off = i - PH_X_F4 - PH_W_F4; }
            float4 v = src[off];
            dst[off * 2]     = __floats2half2_rn(v.x, v.y);
            dst[off * 2 + 1] = __floats2half2_rn(v.z, v.w);
        }
    } else {
        __shared__ float4 stage[128];
        const int blk = blockIdx.x - PREP_BLOCKS;   // 0..31
        const int b = blk >> 4;                     // 0..1
        const int c = blk & 15;                     // 0..15
        const int fc = t & 127;
        const int half = t >> 7;

        const float4* base = (const float4*)(x + ((size_t)b * N_SEQ + c * 128 + half * 64) * EMB);
        float4 s = make_float4(0.f, 0.f, 0.f, 0.f);
        #pragma unroll 8
        for (int n = 0; n < 64; n++) {
            float4 v = base[(size_t)n * (EMB / 4) + fc];
            s.x += v.x; s.y += v.y; s.z += v.z; s.w += v.w;
        }
        if (half == 1) stage[fc] = s;
        __syncthreads();
        if (half == 0) {
            float4 o = stage[fc];
            o.x += s.x; o.y += s.y; o.z += s.z; o.w += s.w;
            *(float4*)(xpart + ((size_t)b * 16 + c) * EMB + fc * 4) = o;
        }
    }
}

// ---------------- fp16 mma.sync GEMM: Q,K = X @ W.T + b (fp16 out) -------------
// CTA tile 128x256, 16 warps (2x8), warp tile 64x32, 3-stage, ldmatrix frags.
#define GBM 128
#define GBN 256
#define BKH 64
#define SAH 72                          // padded row stride in halves
#define A_TILE_H (GBM * SAH)            // 9216 halves
#define B_TILE_H (GBN * SAH)            // 18432 halves
#define A_BYTES  (A_TILE_H * 2)         // 18432
#define STAGE_BYTES ((A_TILE_H + B_TILE_H) * 2)   // 55296
#define NSTAGE 3
#define NKIT (EMB / BKH)                // 8
#define GEMM_SMEM (STAGE_BYTES * NSTAGE)          // 165888

__global__ __launch_bounds__(512, 1)
void qk_gemm_f16(const __half* __restrict__ xh,
                 const __half* __restrict__ wqh, const float* __restrict__ bq,
                 const __half* __restrict__ wkh, const float* __restrict__ bk,
                 __half* __restrict__ Qout, __half* __restrict__ Kout) {
    extern __shared__ __half smh[];
    const int tid  = threadIdx.x;
    const int wid  = tid >> 5;
    const int lane = tid & 31;
    const int wm   = wid >> 3;          // 0..1
    const int wn   = wid & 7;           // 0..7
    const int g    = lane >> 2;         // 0..7
    const int tg   = lane & 3;          // 0..3

    const __half* W    = blockIdx.z ? wkh : wqh;
    const float*  bias = blockIdx.z ? bk  : bq;
    __half*       C    = blockIdx.z ? Kout : Qout;
    const int m0 = blockIdx.x * GBM;
    const int n0 = blockIdx.y * GBN;

    const uint32_t uS = smem_u32(smh);

    float acc[4][4][4];
    #pragma unroll
    for (int i = 0; i < 4; i++)
        #pragma unroll
        for (int j = 0; j < 4; j++)
            #pragma unroll
            for (int k = 0; k < 4; k++) acc[i][j][k] = 0.f;

    // ldmatrix per-lane byte offsets (within a stage)
    uint32_t aOff[4], bOff[2];
    {
        const int ar = (lane & 15);
        const int ac = ((lane >> 4) & 1) * 8;
        #pragma unroll
        for (int mt = 0; mt < 4; mt++)
            aOff[mt] = (uint32_t)(((wm * 64 + mt * 16 + ar) * SAH + ac) * 2);
        const int br = (lane & 7) + ((lane >> 4) & 1) * 8;
        const int bc = ((lane >> 3) & 1) * 8;
        #pragma unroll
        for (int p = 0; p < 2; p++)
            bOff[p] = (uint32_t)(A_BYTES + ((wn * 32 + p * 16 + br) * SAH + bc) * 2);
    }

    const int arow = tid >> 2;          // 0..127
    const int acb  = (tid & 3) * 2;     // A chunk base
    const int brow = tid >> 1;          // 0..255
    const int bcb  = (tid & 1) * 4;     // B chunk base

    auto load_stage = [&](int k0, int s) {
        const uint32_t base = uS + (uint32_t)s * STAGE_BYTES;
        #pragma unroll
        for (int i = 0; i < 2; i++) {
            const int ch = acb + i;
            cp16(base + (uint32_t)(arow * SAH + ch * 8) * 2,
                 xh + (size_t)(m0 + arow) * EMB + k0 + ch * 8);
        }
        #pragma unroll
        for (int i = 0; i < 4; i++) {
            const int ch = bcb + i;
            cp16(base + A_BYTES + (uint32_t)(brow * SAH + ch * 8) * 2,
                 W + (size_t)(n0 + brow) * EMB + k0 + ch * 8);
        }
    };

    load_stage(0, 0);
    cp_commit();
    load_stage(BKH, 1);
    cp_commit();

    #pragma unroll 1
    for (int c = 0; c < NKIT; c++) {
        if (c <= NKIT - 2) { cp_wait<1>(); } else { cp_wait<0>(); }
        __syncthreads();
        if (c + 2 < NKIT) {
            load_stage((c + 2) * BKH, (c + 2) % NSTAGE);
            cp_commit();
        }

        const uint32_t sBase = uS + (uint32_t)(c % NSTAGE) * STAGE_BYTES;

        #pragma unroll
        for (int ks = 0; ks < 4; ks++) {
            const uint32_t kb = ks * 32;            // 16 halves = 32 bytes
            uint32_t af[4][4];
            #pragma unroll
            for (int mt = 0; mt < 4; mt++)
                ldsm_x4(af[mt][0], af[mt][1], af[mt][2], af[mt][3],
                        sBase + aOff[mt] + kb);
            uint32_t bf[2][4];
            #pragma unroll
            for (int p = 0; p < 2; p++)
                ldsm_x4(bf[p][0], bf[p][1], bf[p][2], bf[p][3],
                        sBase + bOff[p] + kb);
            #pragma unroll
            for (int mt = 0; mt < 4; mt++) {
                #pragma unroll
                for (int p = 0; p < 2; p++) {
                    mma_f16(acc[mt][p * 2],     af[mt], bf[p][0], bf[p][1]);
                    mma_f16(acc[mt][p * 2 + 1], af[mt], bf[p][2], bf[p][3]);
                }
            }
        }
    }

    // epilogue: bias add + half2 stores
    #pragma unroll
    for (int mt = 0; mt < 4; mt++) {
        const int r = m0 + wm * 64 + mt * 16 + g;
        #pragma unroll
        for (int nt = 0; nt < 4; nt++) {
            const int cn = n0 + wn * 32 + nt * 8 + tg * 2;
            const float2 bb = *(const float2*)(bias + cn);
            __half2 v0 = __floats2half2_rn(acc[mt][nt][0] + bb.x,
                                           acc[mt][nt][1] + bb.y);
            __half2 v1 = __floats2half2_rn(acc[mt][nt][2] + bb.x,
                                           acc[mt][nt][3] + bb.y);
            *(__half2*)(C + (size_t)r * EMB + cn)       = v0;
            *(__half2*)(C + (size_t)(r + 8) * EMB + cn) = v1;
        }
    }
}

// ---------------- basis: bs[b][j][row] = dot(Wv[row], vec_j) + bv*scale --------
__global__ __launch_bounds__(256)
void basis_kernel(const float* __restrict__ x, const float* __restrict__ xpart,
                  const float* __restrict__ Wv, const float* __restrict__ bv,
                  float* __restrict__ bs) {
    __shared__ float vec[4 * EMB];
    const int b = blockIdx.x;
    const int t = threadIdx.x;
    const int w = t >> 5, lane = t & 31;

    #pragma unroll
    for (int rep = 0; rep < 2; rep++) {
        const int col = t + rep * 256;
        float s = 0.f;
        #pragma unroll
        for (int r = 0; r < 16; r++)
            s += xpart[((size_t)b * 16 + r) * EMB + col];
        vec[col] = s;
    }
    #pragma unroll
    for (int j = 1; j < 4; j++) {
        float2 v = ((const float2*)(x + ((size_t)b * N_SEQ + (j - 1)) * EMB))[t];
        ((float2*)(vec + j * EMB))[t] = v;
    }
    __syncthreads();

    const int row = blockIdx.y * 8 + w;     // 0..511
    const float4* wr = (const float4*)(Wv + (size_t)row * EMB);
    float4 wv[4];
    #pragma unroll
    for (int i = 0; i < 4; i++) wv[i] = wr[lane + 32 * i];

    float a[4];
    #pragma unroll
    for (int j = 0; j < 4; j++) {
        const float4* vr = (const float4*)(vec + j * EMB);
        float s = 0.f;
        #pragma unroll
        for (int i = 0; i < 4; i++) {
            float4 vv = vr[lane + 32 * i];
            s += wv[i].x * vv.x + wv[i].y * vv.y + wv[i].z * vv.z + wv[i].w * vv.w;
        }
        a[j] = s;
    }
    #pragma unroll
    for (int off = 16; off; off >>= 1)
        #pragma unroll
        for (int j = 0; j < 4; j++)
            a[j] += __shfl_xor_sync(0xffffffff, a[j], off);
    if (lane < 4) {
        const int j = lane;
        const float scale = (j == 0) ? (float)N_SEQ : 1.f;
        bs[((size_t)b * 4 + j) * EMB + row] = a[j] + bv[row] * scale;
    }
}

// ---------------- U[b][h][j][eo] = sum_d Wo[eo][h*64+d] * bs[b][j][h*64+d] -----
__global__ __launch_bounds__(256)
void u_kernel(const float* __restrict__ bs, const float* __restrict__ Wo,
              float* __restrict__ U) {
    __shared__ float sWo[128 * 65];
    __shared__ float sbs[4][HD];
    const int bh = blockIdx.x;          // 0..15
    const int b = bh >> 3, h = bh & 7;
    const int eo0 = blockIdx.y * 128;
    const int t = threadIdx.x;

    if (t < 4 * HD) {
        const int j = t >> 6, d = t & 63;
        sbs[j][d] = bs[((size_t)b * 4 + j) * EMB + h * HD + d];
    }
    #pragma unroll
    for (int i = 0; i < 8; i++) {
        const int fi = t + 256 * i;
        const int r = fi >> 4, c4 = fi & 15;
        float4 v = *(const float4*)(Wo + (size_t)(eo0 + r) * EMB + h * HD + c4 * 4);
        float* dst = sWo + r * 65 + c4 * 4;
        dst[0] = v.x; dst[1] = v.y; dst[2] = v.z; dst[3] = v.w;
    }
    __syncthreads();

    const int eo = t & 127;
    const int jp = t >> 7;              // 0/1 -> j pair {0,1} or {2,3}
    const float* wrow = sWo + eo * 65;
    float a0 = 0.f, a1 = 0.f;
    #pragma unroll 8
    for (int d = 0; d < HD; d++) {
        const float wv = wrow[d];
        a0 = fmaf(wv, sbs[jp * 2][d],     a0);
        a1 = fmaf(wv, sbs[jp * 2 + 1][d], a1);
    }
    U[((size_t)(b * NHEAD + h) * 4 + jp * 2)     * EMB + eo0 + eo] = a0;
    U[((size_t)(b * NHEAD + h) * 4 + jp * 2 + 1) * EMB + eo0 + eo] = a1;
}

// ---------------- fused coef + out ----------------------------------------------
__global__ __launch_bounds__(256)
void coef_out_kernel(const __half* __restrict__ Q, const __half* __restrict__ K,
                     const float* __restrict__ U, const float* __restrict__ bo,
                     float* __restrict__ out) {
    const int blk = blockIdx.x;                 // 0..255
    const int b = blk >> 7;
    const int r0 = (blk & 127) * 16;
    const int t = threadIdx.x;
    const int h = t >> 5;                       // warp = head
    const int lane = t & 31;

    float u0[32], u1[32];
    #pragma unroll
    for (int hj = 0; hj < 32; hj++) {
        u0[hj] = U[((size_t)b * 32 + hj) * EMB + t];
        u1[hj] = U[((size_t)b * 32 + hj) * EMB + t + 256];
    }

    __shared__ float sc[16][32];
    const size_t base = ((size_t)b * N_SEQ) * EMB + h * HD;
    #pragma unroll 2
    for (int rr = 0; rr < 16; rr++) {
        const int r = r0 + rr;
        const __half2 q2 = ((const __half2*)(Q + base + (size_t)r * EMB))[lane];
        const float2 qf = __half22float2(q2);
        float v[3];
        bool valid[3];
        #pragma unroll
        for (int c = 0; c < 3; c++) {
            const int kr = r + c - 1;
            valid[c] = (kr >= 0 && kr < N_SEQ);
            if (valid[c]) {
                const __half2 k2 = ((const __half2*)(K + base + (size_t)kr * EMB))[lane];
                const float2 kf = __half22float2(k2);
                v[c] = qf.x * kf.x + qf.y * kf.y;
            } else v[c] = 0.f;
        }
        #pragma unroll
        for (int off = 16; off; off >>= 1)
            #pragma unroll
            for (int c = 0; c < 3; c++)
                v[c] += __shfl_xor_sync(0xffffffff, v[c], off);
        float e[3];
        #pragma unroll
        for (int c = 0; c < 3; c++)
            e[c] = valid[c] ? (expf(v[c]) - 1.f) : 0.f;
        const float inv = 1.f / ((float)N_SEQ + e[0] + e[1] + e[2]);
        if (lane < 4)
            sc[rr][h * 4 + lane] = (lane == 0) ? inv : inv * e[lane - 1];
    }
    __syncthreads();

    const float bo0 = bo[t], bo1 = bo[t + 256];
    #pragma unroll 2
    for (int rr = 0; rr < 16; rr++) {
        float a0 = bo0, a1 = bo1;
        #pragma unroll
        for (int hj = 0; hj < 32; hj++) {
            const float c = sc[rr][hj];
            a0 = fmaf(c, u0[hj], a0);
            a1 = fmaf(c, u1[hj], a1);
        }
        const size_t ob = ((size_t)b * N_SEQ + r0 + rr) * EMB;
        out[ob + t]       = a0;
        out[ob + t + 256] = a1;
    }
}

// ---------------- launch ----------------------------------------------------------
extern "C" void kernel_launch(void* const* d_in, const int* in_sizes, int n_in,
                              void* d_out, int out_size) {
    const float* x  = (const float*)d_in[0];
    const float* Wq = (const float*)d_in[1];
    const float* bq = (const float*)d_in[2];
    const float* Wk = (const float*)d_in[3];
    const float* bk = (const float*)d_in[4];
    const float* Wv = (const float*)d_in[5];
    const float* bv = (const float*)d_in[6];
    const float* Wo = (const float*)d_in[7];
    const float* bo = (const float*)d_in[8];
    float* outp = (float*)d_out;

    __half *xh, *wqh, *wkh, *Qp, *Kp;
    float *xpp, *bsp, *Up;
    cudaGetSymbolAddress((void**)&xh,  g_xh);
    cudaGetSymbolAddress((void**)&wqh, g_wqh);
    cudaGetSymbolAddress((void**)&wkh, g_wkh);
    cudaGetSymbolAddress((void**)&Qp,  g_Qh);
    cudaGetSymbolAddress((void**)&Kp,  g_Kh);
    cudaGetSymbolAddress((void**)&xpp, g_xpart);
    cudaGetSymbolAddress((void**)&bsp, g_bs);
    cudaGetSymbolAddress((void**)&Up,  g_U);

    cudaFuncSetAttribute(qk_gemm_f16,
                         cudaFuncAttributeMaxDynamicSharedMemorySize, GEMM_SMEM);

    // fused fp16 convert + x partial sums (both branches' prerequisites)
    prep_fused<<<PREP_BLOCKS + 32, 256>>>(x, Wq, Wk, xh, wqh, wkh, xpp);

    // Fork: side branch (basis -> U) runs concurrently with the Q/K GEMM.
    cudaEventRecord(g_ss.evF, 0);
    cudaStreamWaitEvent(g_ss.s2, g_ss.evF, 0);

    // Branch A (main stream): Q/K GEMM
    qk_gemm_f16<<<dim3(M_ROWS / GBM, EMB / GBN, 2), 512, GEMM_SMEM>>>(
        xh, wqh, bq, wkh, bk, Qp, Kp);

    // Branch B (side stream): basis -> U
    basis_kernel<<<dim3(BATCH, 64), 256, 0, g_ss.s2>>>(x, xpp, Wv, bv, bsp);
    u_kernel<<<dim3(BATCH * NHEAD, 4), 256, 0, g_ss.s2>>>(bsp, Wo, Up);

    // Join, then final combine
    cudaEventRecord(g_ss.evJ, g_ss.s2);
    cudaStreamWaitEvent(0, g_ss.evJ, 0);

    coef_out_kernel<<<256, 256>>>(Qp, Kp, Up, bo, outp);
}